// round 8
// baseline (speedup 1.0000x reference)
#include <cuda_runtime.h>
#include <cstdint>

typedef unsigned long long u64;
typedef long long           i64;

// ---------------------------------------------------------------------------
#define B_   256
#define T_   100
#define I_   2048
#define H_   2048
#define M_   (B_ * T_)      // 25600

#define BM   64
#define BN   64
#define MT   (M_ / BM)      // 400
#define NT   (H_ / BN)      // 32
#define NCHUNK (I_ / 128)   // 16 K-chunks of 128 bytes

#define PLANE 8192          // 64 rows x 128 B per digit slice
#define STAGE (8 * PLANE)   // 4 A planes + 4 B planes = 64 KiB
#define DSMEM (2 * STAGE)   // 128 KiB double buffered

// Static device scratch (no allocations)
__device__ __align__(16) int8_t g_Xs[4ll * M_ * I_];   // 200 MiB digit planes
__device__ __align__(16) int8_t g_Ws[4ll * H_ * I_];   // 16 MiB
__device__ i64   g_SX[M_];
__device__ i64   g_SW[H_];
__device__ float g_sxf[M_];
__device__ float g_swf[H_];
__device__ float g_proj[(size_t)M_ * H_];              // 200 MiB
__device__ float g_probe_sink[148 * 256];              // probe output (dummy)

// ---------------------------------------------------------------------------
// helpers (all family-common PTX: sm_80-class, no tcgen05/TMA)
// ---------------------------------------------------------------------------
__device__ __forceinline__ uint32_t smem_u32(const void* p) {
    uint32_t a;
    asm("{ .reg .u64 t; cvta.to.shared.u64 t, %1; cvt.u32.u64 %0, t; }" : "=r"(a) : "l"(p));
    return a;
}
__device__ __forceinline__ uint32_t sw128(uint32_t o) { return o ^ ((o >> 3) & 0x70); }

__device__ __forceinline__ void ldsm4(uint32_t& r0, uint32_t& r1, uint32_t& r2, uint32_t& r3,
                                      uint32_t a) {
    asm volatile("ldmatrix.sync.aligned.m8n8.x4.shared.b16 {%0,%1,%2,%3}, [%4];"
                 : "=r"(r0), "=r"(r1), "=r"(r2), "=r"(r3) : "r"(a));
}
__device__ __forceinline__ void cpa16(uint32_t d, const void* s) {
    asm volatile("cp.async.cg.shared.global [%0], [%1], 16;" :: "r"(d), "l"(s));
}
#define CP_COMMIT() asm volatile("cp.async.commit_group;")
#define CP_WAIT1()  asm volatile("cp.async.wait_group 1;")
#define CP_WAIT0()  asm volatile("cp.async.wait_group 0;")

#define MMA(d, a, b) \
    asm volatile("mma.sync.aligned.m16n8k32.row.col.s32.s8.s8.s32 " \
                 "{%0,%1,%2,%3}, {%4,%5,%6,%7}, {%8,%9}, {%0,%1,%2,%3};" \
                 : "+r"((d)[0]), "+r"((d)[1]), "+r"((d)[2]), "+r"((d)[3]) \
                 : "r"((a)[0]), "r"((a)[1]), "r"((a)[2]), "r"((a)[3]), \
                   "r"((b)[0]), "r"((b)[1]))

// ---------------------------------------------------------------------------
// Split: per-row power-of-2 scale, 4 unsigned base-128 digits of (u+1)
// (all fp32 steps exact), plane layout dst[slice][row][k], per-row digit sum.
// ---------------------------------------------------------------------------
__global__ __launch_bounds__(256)
void split_kernel(const float* __restrict__ src, int8_t* __restrict__ dst,
                  i64* __restrict__ sumT, float* __restrict__ scl, i64 sstride)
{
    __shared__ float smax[256];
    __shared__ i64   ssum[256];
    __shared__ float s_inv;

    const int r = blockIdx.x;
    const int tid = threadIdx.x;
    const float* row = src + (size_t)r * I_;

    float mx = 0.0f;
    #pragma unroll
    for (int it = 0; it < I_ / 256; it++) mx = fmaxf(mx, fabsf(row[tid + it * 256]));
    smax[tid] = mx;
    __syncthreads();
    for (int s = 128; s > 0; s >>= 1) {
        if (tid < s) smax[tid] = fmaxf(smax[tid], smax[tid + s]);
        __syncthreads();
    }
    if (tid == 0) {
        int e = 0;
        if (smax[0] > 0.0f) frexpf(smax[0], &e);   // max = f*2^e, f in [0.5,1)
        s_inv = ldexpf(1.0f, -e);
        scl[r] = ldexpf(1.0f, e - 27);
    }
    __syncthreads();
    const float sinv = s_inv;

    i64 acc = 0;
    #pragma unroll
    for (int it = 0; it < I_ / 256; it++) {
        int k = tid + it * 256;
        float u  = row[k] * sinv;                 // exact, |u| < 1
        float t0 = u * 64.0f;   float f0 = floorf(t0); float r1 = t0 - f0;
        float t1 = r1 * 128.0f; float f1 = floorf(t1); float r2 = t1 - f1;
        float t2 = r2 * 128.0f; float f2 = floorf(t2); float r3 = t2 - f2;
        float f3 = floorf(r3 * 128.0f);
        int c0 = (int)f0 + 64;                    // [0,127]
        int c1 = (int)f1, c2 = (int)f2, c3 = (int)f3;

        acc += (i64)(((c0 * 128 + c1) * 128 + c2) * 128 + c3);

        i64 base = (i64)r * I_ + k;
        dst[0 * sstride + base] = (int8_t)c0;
        dst[1 * sstride + base] = (int8_t)c1;
        dst[2 * sstride + base] = (int8_t)c2;
        dst[3 * sstride + base] = (int8_t)c3;
    }

    ssum[tid] = acc;
    __syncthreads();
    for (int s = 128; s > 0; s >>= 1) {
        if (tid < s) ssum[tid] += ssum[tid + s];
        __syncthreads();
    }
    if (tid == 0) sumT[r] = ssum[0];
}

// ---------------------------------------------------------------------------
// GEMM: warp-level int8 mma.sync (unchanged from R7 best: 21.65 ms).
// ---------------------------------------------------------------------------
__global__ __launch_bounds__(256, 1)
void lif_gemm_imma_kernel(const float* __restrict__ bias, float* __restrict__ proj)
{
    extern __shared__ int8_t smem[];
    const uint32_t sb = smem_u32(smem);
    const int tid  = threadIdx.x;
    const int lane = tid & 31;
    const int wid  = tid >> 5;
    const int wm   = wid >> 1;    // 0..3 -> M group (16 rows)
    const int wn   = wid & 1;     // 0..1 -> N group (32 cols)
    const int bx = blockIdx.x;    // N tile
    const int by = blockIdx.y;    // M tile

    const int q  = lane >> 3;
    const int l7 = lane & 7;

    int D[6][4][4];
    #pragma unroll
    for (int s = 0; s < 6; s++)
        #pragma unroll
        for (int nt = 0; nt < 4; nt++)
            #pragma unroll
            for (int e = 0; e < 4; e++) D[s][nt][e] = 0;

#define LOAD_CHUNK(c) do {                                                        \
    uint32_t stg = sb + ((c) & 1) * STAGE;                                        \
    _Pragma("unroll")                                                             \
    for (int v = 0; v < 16; v++) {                                                \
        int id = v * 256 + tid;                                                   \
        int slice = (id >> 9) & 3;                                                \
        int idx = id & 511;                                                       \
        int row = idx >> 3, x = idx & 7;                                          \
        uint32_t dst = stg + ((id >> 11) ? 4 * PLANE : 0) + slice * PLANE         \
                     + sw128((uint32_t)(row * 128 + x * 16));                     \
        const int8_t* src = (id >> 11)                                            \
            ? (g_Ws + (i64)slice * H_ * I_ + (i64)(bx * BN + row) * I_ + (c) * 128 + x * 16) \
            : (g_Xs + (i64)slice * M_ * I_ + (i64)(by * BM + row) * I_ + (c) * 128 + x * 16); \
        cpa16(dst, src);                                                          \
    }                                                                             \
    CP_COMMIT();                                                                  \
} while (0)

#define PP(i, j, s) {                                                             \
    _Pragma("unroll")                                                             \
    for (int nt = 0; nt < 4; nt++) MMA(D[s][nt], A[i], Bt[j][nt]);                \
}

#define COMPUTE_CHUNK(c) do {                                                     \
    uint32_t stg = sb + ((c) & 1) * STAGE;                                        \
    _Pragma("unroll")                                                             \
    for (int ks = 0; ks < 4; ks++) {                                              \
        uint32_t A[4][4];                                                         \
        _Pragma("unroll")                                                         \
        for (int sl = 0; sl < 4; sl++) {                                          \
            int row = wm * 16 + ((q & 1) << 3) + l7;                              \
            uint32_t ad = stg + sl * PLANE                                        \
                        + sw128((uint32_t)(row * 128 + ks * 32 + (q >> 1) * 16)); \
            ldsm4(A[sl][0], A[sl][1], A[sl][2], A[sl][3], ad);                    \
        }                                                                         \
        uint32_t Bt[4][4][2];                                                     \
        _Pragma("unroll")                                                         \
        for (int sl = 0; sl < 4; sl++) {                                          \
            _Pragma("unroll")                                                     \
            for (int g = 0; g < 2; g++) {                                         \
                int n = wn * 32 + g * 16 + ((q >> 1) << 3) + l7;                  \
                uint32_t bd = stg + 4 * PLANE + sl * PLANE                        \
                            + sw128((uint32_t)(n * 128 + ks * 32 + (q & 1) * 16));\
                uint32_t r0, r1, r2, r3;                                          \
                ldsm4(r0, r1, r2, r3, bd);                                        \
                Bt[sl][2 * g][0] = r0; Bt[sl][2 * g][1] = r1;                     \
                Bt[sl][2 * g + 1][0] = r2; Bt[sl][2 * g + 1][1] = r3;             \
            }                                                                     \
        }                                                                         \
        PP(0,0,0) PP(0,1,1) PP(1,0,1) PP(0,2,2) PP(1,1,2) PP(2,0,2)               \
        PP(0,3,3) PP(1,2,3) PP(2,1,3) PP(3,0,3) PP(1,3,4) PP(2,2,4)               \
        PP(3,1,4) PP(2,3,5) PP(3,2,5)                                             \
    }                                                                             \
} while (0)

    LOAD_CHUNK(0);
    #pragma unroll 1
    for (int c = 0; c < NCHUNK; c++) {
        if (c + 1 < NCHUNK) {
            LOAD_CHUNK(c + 1);
            CP_WAIT1();
        } else {
            CP_WAIT0();
        }
        __syncthreads();
        COMPUTE_CHUNK(c);
        __syncthreads();
    }

    // ---- epilogue: exact recombination ----
    const int mrow0 = by * BM + wm * 16 + (lane >> 2);
    const int col0  = bx * BN + wn * 32 + 2 * (lane & 3);

    #pragma unroll
    for (int half = 0; half < 2; half++) {
        int m = mrow0 + 8 * half;
        i64 SXm = g_SX[m];
        double sx = (double)g_sxf[m];
        float* orow = proj + (size_t)m * H_ + col0;
        #pragma unroll
        for (int nt = 0; nt < 4; nt++) {
            float v[2];
            #pragma unroll
            for (int dj = 0; dj < 2; dj++) {
                int h = col0 + 8 * nt + dj;
                int e = 2 * half + dj;
                u64 P = ((u64)(uint32_t)D[0][nt][e] << 42)
                      + ((u64)(uint32_t)D[1][nt][e] << 35)
                      + ((u64)(uint32_t)D[2][nt][e] << 28)
                      + ((u64)(uint32_t)D[3][nt][e] << 21)
                      + ((u64)(uint32_t)D[4][nt][e] << 14)
                      + ((u64)(uint32_t)D[5][nt][e] << 7);
                i64 Pp = (i64)(P - ((u64)(SXm + g_SW[h]) << 27));
                double sc = sx * (double)g_swf[h];
                v[dj] = (float)((double)Pp * sc + (double)bias[h]);
            }
            *(float2*)(orow + 8 * nt) = make_float2(v[0], v[1]);
        }
    }
#undef LOAD_CHUNK
#undef COMPUTE_CHUNK
#undef PP
}

// ---------------------------------------------------------------------------
// LIF scan
// ---------------------------------------------------------------------------
__global__ __launch_bounds__(256)
void lif_scan_kernel(const float* __restrict__ proj, float* __restrict__ out)
{
    int idx = blockIdx.x * blockDim.x + threadIdx.x;
    if (idx >= B_ * H_) return;
    int b = idx / H_;
    int h = idx % H_;
    const size_t base = (size_t)b * T_ * H_ + h;
    float hs = 0.0f;
    #pragma unroll 4
    for (int t = 0; t < T_; t++) {
        float p = proj[base + (size_t)t * H_];
        hs = __fadd_rn(__fmul_rn(0.9f, hs), p);
        float sp = (hs >= 1.0f) ? 1.0f : 0.0f;
        out[base + (size_t)t * H_] = sp;
        hs = __fmul_rn(hs, __fsub_rn(1.0f, sp));
    }
    out[(size_t)B_ * T_ * H_ + (size_t)b * H_ + h] = hs;
}

// ---------------------------------------------------------------------------
// PROBE: bf16 HMMA issue-rate measurement. Register-resident, 8 independent
// accumulator fragments, 400 iterations x 8 mma per warp. Deterministic dummy
// output to g_probe_sink (never read by anything else).
// If mma.bf16 is NATIVE: dur ~10-40us, tensor% high.
// If EMULATED: dur ~300-1100us, fma% high, tensor% ~0.
// ---------------------------------------------------------------------------
__global__ __launch_bounds__(256)
void hmma_bf16_probe_kernel(float* __restrict__ sink)
{
    const int tid = threadIdx.x;
    // constant operands (same for all threads, deterministic)
    uint32_t a0 = 0x3f803f80u, a1 = 0x3f003f00u, a2 = 0xbf80bf80u, a3 = 0x3e803e80u;
    uint32_t b0 = 0x3f803f00u, b1 = 0xbf003f80u;

    float d[8][4];
    #pragma unroll
    for (int i = 0; i < 8; i++) {
        d[i][0] = (float)(tid & 3) * 0.25f;
        d[i][1] = 0.5f; d[i][2] = -0.25f; d[i][3] = 0.125f;
    }

    #pragma unroll 1
    for (int it = 0; it < 400; it++) {
        #pragma unroll
        for (int i = 0; i < 8; i++) {
            asm volatile(
                "mma.sync.aligned.m16n8k16.row.col.f32.bf16.bf16.f32 "
                "{%0,%1,%2,%3}, {%4,%5,%6,%7}, {%8,%9}, {%0,%1,%2,%3};"
                : "+f"(d[i][0]), "+f"(d[i][1]), "+f"(d[i][2]), "+f"(d[i][3])
                : "r"(a0), "r"(a1), "r"(a2), "r"(a3), "r"(b0), "r"(b1));
        }
    }

    float acc = 0.0f;
    #pragma unroll
    for (int i = 0; i < 8; i++)
        acc += d[i][0] - d[i][1] + d[i][2] - d[i][3];
    sink[blockIdx.x * 256 + tid] = acc;
}

// ---------------------------------------------------------------------------
extern "C" void kernel_launch(void* const* d_in, const int* in_sizes, int n_in,
                              void* d_out, int out_size)
{
    const float* X    = (const float*)d_in[0];
    const float* W    = (const float*)d_in[1];
    const float* bias = (const float*)d_in[2];
    float* out = (float*)d_out;

    int8_t *Xs, *Ws;
    i64 *SX, *SW;
    float *sxf, *swf, *proj, *sink;
    cudaGetSymbolAddress((void**)&Xs, g_Xs);
    cudaGetSymbolAddress((void**)&Ws, g_Ws);
    cudaGetSymbolAddress((void**)&SX, g_SX);
    cudaGetSymbolAddress((void**)&SW, g_SW);
    cudaGetSymbolAddress((void**)&sxf, g_sxf);
    cudaGetSymbolAddress((void**)&swf, g_swf);
    cudaGetSymbolAddress((void**)&proj, g_proj);
    cudaGetSymbolAddress((void**)&sink, g_probe_sink);

    cudaFuncSetAttribute(lif_gemm_imma_kernel,
                         cudaFuncAttributeMaxDynamicSharedMemorySize, DSMEM);

    // digit splits
    split_kernel<<<M_, 256>>>(X, Xs, SX, sxf, (i64)M_ * I_);
    split_kernel<<<H_, 256>>>(W, Ws, SW, swf, (i64)H_ * I_);

    // int8 warp-MMA GEMM with exact recombination
    dim3 ggrid(NT, MT);   // (32, 400)
    lif_gemm_imma_kernel<<<ggrid, 256, DSMEM>>>(bias, proj);

    // LIF scan
    lif_scan_kernel<<<(B_ * H_ + 255) / 256, 256>>>(proj, out);

    // bf16 HMMA rate probe — LAST launch (the profiled one)
    hmma_bf16_probe_kernel<<<148, 256>>>(sink);
}

// round 9
// speedup vs baseline: 2.2135x; 2.2135x over previous
#include <cuda_runtime.h>
#include <cstdint>

typedef unsigned long long u64;
typedef long long           i64;

// ---------------------------------------------------------------------------
#define B_   256
#define T_   100
#define I_   2048
#define H_   2048
#define M_   (B_ * T_)      // 25600

#define BM   64
#define BN   64
#define MT   (M_ / BM)      // 400
#define NT   (H_ / BN)      // 32
#define NCHUNK (I_ / 64)    // 32 K-chunks of 64 bf16 elements (128 bytes/row)

#define PLANE 8192          // 64 rows x 128 B per digit slice
#define STAGE (8 * PLANE)   // 4 A planes + 4 B planes = 64 KiB
#define DSMEM (2 * STAGE)   // 128 KiB double buffered

// Static device scratch (no allocations). Digits stored as bf16 bit patterns.
__device__ __align__(16) unsigned short g_Xs[4ll * M_ * I_];   // 400 MiB
__device__ __align__(16) unsigned short g_Ws[4ll * H_ * I_];   // 32 MiB
__device__ i64   g_SX[M_];
__device__ i64   g_SW[H_];
__device__ float g_sxf[M_];
__device__ float g_swf[H_];
__device__ float g_proj[(size_t)M_ * H_];                      // 200 MiB

// ---------------------------------------------------------------------------
// helpers (all family-common PTX)
// ---------------------------------------------------------------------------
__device__ __forceinline__ uint32_t smem_u32(const void* p) {
    uint32_t a;
    asm("{ .reg .u64 t; cvta.to.shared.u64 t, %1; cvt.u32.u64 %0, t; }" : "=r"(a) : "l"(p));
    return a;
}
__device__ __forceinline__ uint32_t sw128(uint32_t o) { return o ^ ((o >> 3) & 0x70); }

__device__ __forceinline__ void ldsm4(uint32_t& r0, uint32_t& r1, uint32_t& r2, uint32_t& r3,
                                      uint32_t a) {
    asm volatile("ldmatrix.sync.aligned.m8n8.x4.shared.b16 {%0,%1,%2,%3}, [%4];"
                 : "=r"(r0), "=r"(r1), "=r"(r2), "=r"(r3) : "r"(a));
}
__device__ __forceinline__ void cpa16(uint32_t d, const void* s) {
    asm volatile("cp.async.cg.shared.global [%0], [%1], 16;" :: "r"(d), "l"(s));
}
#define CP_COMMIT() asm volatile("cp.async.commit_group;")
#define CP_WAIT1()  asm volatile("cp.async.wait_group 1;")
#define CP_WAIT0()  asm volatile("cp.async.wait_group 0;")

// bf16 HMMA, fp32 accumulate (accumulation exact for our integer digit values)
#define MMA(d, a, b) \
    asm volatile("mma.sync.aligned.m16n8k16.row.col.f32.bf16.bf16.f32 " \
                 "{%0,%1,%2,%3}, {%4,%5,%6,%7}, {%8,%9}, {%0,%1,%2,%3};" \
                 : "+f"((d)[0]), "+f"((d)[1]), "+f"((d)[2]), "+f"((d)[3]) \
                 : "r"((a)[0]), "r"((a)[1]), "r"((a)[2]), "r"((a)[3]), \
                   "r"((b)[0]), "r"((b)[1]))

// ---------------------------------------------------------------------------
// Split: per-row power-of-2 scale, 4 unsigned base-128 digits of (u+1)
// (all fp32 steps exact). Digits stored as bf16 (integers <=127: exact).
// Layout dst[slice][row][k]. Per-row digit sum SX = (u+1)*2^27 summed over k.
// ---------------------------------------------------------------------------
__global__ __launch_bounds__(256)
void split_kernel(const float* __restrict__ src, unsigned short* __restrict__ dst,
                  i64* __restrict__ sumT, float* __restrict__ scl, i64 sstride)
{
    __shared__ float smax[256];
    __shared__ i64   ssum[256];
    __shared__ float s_inv;

    const int r = blockIdx.x;
    const int tid = threadIdx.x;
    const float* row = src + (size_t)r * I_;

    float mx = 0.0f;
    #pragma unroll
    for (int it = 0; it < I_ / 256; it++) mx = fmaxf(mx, fabsf(row[tid + it * 256]));
    smax[tid] = mx;
    __syncthreads();
    for (int s = 128; s > 0; s >>= 1) {
        if (tid < s) smax[tid] = fmaxf(smax[tid], smax[tid + s]);
        __syncthreads();
    }
    if (tid == 0) {
        int e = 0;
        if (smax[0] > 0.0f) frexpf(smax[0], &e);   // max = f*2^e, f in [0.5,1)
        s_inv = ldexpf(1.0f, -e);
        scl[r] = ldexpf(1.0f, e - 27);
    }
    __syncthreads();
    const float sinv = s_inv;

    i64 acc = 0;
    #pragma unroll
    for (int it = 0; it < I_ / 256; it++) {
        int k = tid + it * 256;
        float u  = row[k] * sinv;                 // exact, |u| < 1
        float t0 = u * 64.0f;   float f0 = floorf(t0); float r1 = t0 - f0;
        float t1 = r1 * 128.0f; float f1 = floorf(t1); float r2 = t1 - f1;
        float t2 = r2 * 128.0f; float f2 = floorf(t2); float r3 = t2 - f2;
        float f3 = floorf(r3 * 128.0f);
        int c0 = (int)f0 + 64;                    // [0,127]
        int c1 = (int)f1, c2 = (int)f2, c3 = (int)f3;

        acc += (i64)(((c0 * 128 + c1) * 128 + c2) * 128 + c3);

        i64 base = (i64)r * I_ + k;
        // int -> bf16 bits (exact for integers <= 127): fp32 bits >> 16
        dst[0 * sstride + base] = (unsigned short)(__float_as_uint((float)c0) >> 16);
        dst[1 * sstride + base] = (unsigned short)(__float_as_uint((float)c1) >> 16);
        dst[2 * sstride + base] = (unsigned short)(__float_as_uint((float)c2) >> 16);
        dst[3 * sstride + base] = (unsigned short)(__float_as_uint((float)c3) >> 16);
    }

    ssum[tid] = acc;
    __syncthreads();
    for (int s = 128; s > 0; s >>= 1) {
        if (tid < s) ssum[tid] += ssum[tid + s];
        __syncthreads();
    }
    if (tid == 0) sumT[r] = ssum[0];
}

// ---------------------------------------------------------------------------
// GEMM: bf16 HMMA, 15 digit pairs (i+j<=5) into 6 fp32 accumulators (exact
// integers), folded into one u64 per element every 128 K (exactness bound:
// 4 pairs * 128 * 127^2 = 8.26e6 < 2^24). Exact mod-2^64 recombination.
// CTA 64x64, 8 warps (4M x 2N), warp tile m16 x n32, double-buffered chunks.
// ---------------------------------------------------------------------------
__global__ __launch_bounds__(256, 1)
void lif_gemm_hmma_kernel(const float* __restrict__ bias, float* __restrict__ proj)
{
    extern __shared__ int8_t smem[];
    const uint32_t sb = smem_u32(smem);
    const int tid  = threadIdx.x;
    const int lane = tid & 31;
    const int wid  = tid >> 5;
    const int wm   = wid >> 1;    // 0..3 -> M group (16 rows)
    const int wn   = wid & 1;     // 0..1 -> N group (32 cols)
    const int bx = blockIdx.x;    // N tile
    const int by = blockIdx.y;    // M tile

    const int q  = lane >> 3;
    const int l7 = lane & 7;

    float D[6][4][4];
    u64   P[4][4];
    #pragma unroll
    for (int s = 0; s < 6; s++)
        #pragma unroll
        for (int nt = 0; nt < 4; nt++)
            #pragma unroll
            for (int e = 0; e < 4; e++) D[s][nt][e] = 0.0f;
    #pragma unroll
    for (int nt = 0; nt < 4; nt++)
        #pragma unroll
        for (int e = 0; e < 4; e++) P[nt][e] = 0ull;

#define LOAD_CHUNK(c) do {                                                        \
    uint32_t stg = sb + ((c) & 1) * STAGE;                                        \
    _Pragma("unroll")                                                             \
    for (int v = 0; v < 16; v++) {                                                \
        int id = v * 256 + tid;                                                   \
        int slice = (id >> 9) & 3;                                                \
        int idx = id & 511;                                                       \
        int row = idx >> 3, x = idx & 7;                                          \
        uint32_t dst = stg + ((id >> 11) ? 4 * PLANE : 0) + slice * PLANE         \
                     + sw128((uint32_t)(row * 128 + x * 16));                     \
        const unsigned short* src = (id >> 11)                                    \
            ? (g_Ws + (i64)slice * H_ * I_ + (i64)(bx * BN + row) * I_ + (c) * 64 + x * 8) \
            : (g_Xs + (i64)slice * M_ * I_ + (i64)(by * BM + row) * I_ + (c) * 64 + x * 8); \
        cpa16(dst, src);                                                          \
    }                                                                             \
    CP_COMMIT();                                                                  \
} while (0)

#define PP(i, j, s) {                                                             \
    _Pragma("unroll")                                                             \
    for (int nt = 0; nt < 4; nt++) MMA(D[s][nt], A[i], Bt[j][nt]);                \
}

// chunk = 64 bf16 K-elems (128 B rows); ks selects k16 (32 B); 16 B = k8 half.
#define COMPUTE_CHUNK(c) do {                                                     \
    uint32_t stg = sb + ((c) & 1) * STAGE;                                        \
    _Pragma("unroll")                                                             \
    for (int ks = 0; ks < 4; ks++) {                                              \
        uint32_t A[4][4];                                                         \
        _Pragma("unroll")                                                         \
        for (int sl = 0; sl < 4; sl++) {                                          \
            int row = wm * 16 + ((q & 1) << 3) + l7;                              \
            uint32_t ad = stg + sl * PLANE                                        \
                        + sw128((uint32_t)(row * 128 + ks * 32 + (q >> 1) * 16)); \
            ldsm4(A[sl][0], A[sl][1], A[sl][2], A[sl][3], ad);                    \
        }                                                                         \
        uint32_t Bt[4][4][2];                                                     \
        _Pragma("unroll")                                                         \
        for (int sl = 0; sl < 4; sl++) {                                          \
            _Pragma("unroll")                                                     \
            for (int g = 0; g < 2; g++) {                                         \
                int n = wn * 32 + g * 16 + ((q & 1) << 3) + l7;                   \
                uint32_t bd = stg + 4 * PLANE + sl * PLANE                        \
                            + sw128((uint32_t)(n * 128 + ks * 32 + (q >> 1) * 16));\
                uint32_t r0, r1, r2, r3;                                          \
                ldsm4(r0, r1, r2, r3, bd);                                        \
                Bt[sl][2 * g][0] = r0;     Bt[sl][2 * g][1] = r2;                 \
                Bt[sl][2 * g + 1][0] = r1; Bt[sl][2 * g + 1][1] = r3;             \
            }                                                                     \
        }                                                                         \
        PP(0,0,0) PP(0,1,1) PP(1,0,1) PP(0,2,2) PP(1,1,2) PP(2,0,2)               \
        PP(0,3,3) PP(1,2,3) PP(2,1,3) PP(3,0,3) PP(1,3,4) PP(2,2,4)               \
        PP(3,1,4) PP(2,3,5) PP(3,2,5)                                             \
    }                                                                             \
} while (0)

// Fold fp32 accumulators (exact integers < 2^24) into u64 with weights 2^(42-7s).
#define FOLD() do {                                                               \
    _Pragma("unroll")                                                             \
    for (int nt = 0; nt < 4; nt++) {                                              \
        _Pragma("unroll")                                                         \
        for (int e = 0; e < 4; e++) {                                             \
            u64 p = ((u64)(uint32_t)(int)D[0][nt][e] << 42)                       \
                  + ((u64)(uint32_t)(int)D[1][nt][e] << 35)                       \
                  + ((u64)(uint32_t)(int)D[2][nt][e] << 28)                       \
                  + ((u64)(uint32_t)(int)D[3][nt][e] << 21)                       \
                  + ((u64)(uint32_t)(int)D[4][nt][e] << 14)                       \
                  + ((u64)(uint32_t)(int)D[5][nt][e] << 7);                       \
            P[nt][e] += p;                                                        \
            _Pragma("unroll")                                                     \
            for (int s = 0; s < 6; s++) D[s][nt][e] = 0.0f;                       \
        }                                                                         \
    }                                                                             \
} while (0)

    LOAD_CHUNK(0);
    #pragma unroll 1
    for (int c = 0; c < NCHUNK; c++) {
        if (c + 1 < NCHUNK) {
            LOAD_CHUNK(c + 1);
            CP_WAIT1();
        } else {
            CP_WAIT0();
        }
        __syncthreads();
        COMPUTE_CHUNK(c);
        __syncthreads();
        if (c & 1) FOLD();      // every 128 K elements: exactness bound holds
    }

    // ---- epilogue: exact recombination (identical algebra to int8 version) ----
    const int mrow0 = by * BM + wm * 16 + (lane >> 2);
    const int col0  = bx * BN + wn * 32 + 2 * (lane & 3);

    #pragma unroll
    for (int half = 0; half < 2; half++) {
        int m = mrow0 + 8 * half;
        i64 SXm = g_SX[m];
        double sx = (double)g_sxf[m];
        float* orow = proj + (size_t)m * H_ + col0;
        #pragma unroll
        for (int nt = 0; nt < 4; nt++) {
            float v[2];
            #pragma unroll
            for (int dj = 0; dj < 2; dj++) {
                int h = col0 + 8 * nt + dj;
                int e = 2 * half + dj;
                // true*2^54 = P - 2^27*(SX+SW) + K*2^54;  K*2^54 == 0 mod 2^64
                i64 Pp = (i64)(P[nt][e] - ((u64)(SXm + g_SW[h]) << 27));
                double sc = sx * (double)g_swf[h];   // product of powers of 2: exact
                v[dj] = (float)((double)Pp * sc + (double)bias[h]);
            }
            *(float2*)(orow + 8 * nt) = make_float2(v[0], v[1]);
        }
    }
#undef LOAD_CHUNK
#undef COMPUTE_CHUNK
#undef PP
#undef FOLD
}

// ---------------------------------------------------------------------------
// LIF scan (measured ~67us, DRAM 70%)
// ---------------------------------------------------------------------------
__global__ __launch_bounds__(256)
void lif_scan_kernel(const float* __restrict__ proj, float* __restrict__ out)
{
    int idx = blockIdx.x * blockDim.x + threadIdx.x;
    if (idx >= B_ * H_) return;
    int b = idx / H_;
    int h = idx % H_;
    const size_t base = (size_t)b * T_ * H_ + h;
    float hs = 0.0f;
    #pragma unroll 4
    for (int t = 0; t < T_; t++) {
        float p = proj[base + (size_t)t * H_];
        hs = __fadd_rn(__fmul_rn(0.9f, hs), p);
        float sp = (hs >= 1.0f) ? 1.0f : 0.0f;
        out[base + (size_t)t * H_] = sp;
        hs = __fmul_rn(hs, __fsub_rn(1.0f, sp));
    }
    out[(size_t)B_ * T_ * H_ + (size_t)b * H_ + h] = hs;
}

// ---------------------------------------------------------------------------
extern "C" void kernel_launch(void* const* d_in, const int* in_sizes, int n_in,
                              void* d_out, int out_size)
{
    const float* X    = (const float*)d_in[0];
    const float* W    = (const float*)d_in[1];
    const float* bias = (const float*)d_in[2];
    float* out = (float*)d_out;

    unsigned short *Xs, *Ws;
    i64 *SX, *SW;
    float *sxf, *swf, *proj;
    cudaGetSymbolAddress((void**)&Xs, g_Xs);
    cudaGetSymbolAddress((void**)&Ws, g_Ws);
    cudaGetSymbolAddress((void**)&SX, g_SX);
    cudaGetSymbolAddress((void**)&SW, g_SW);
    cudaGetSymbolAddress((void**)&sxf, g_sxf);
    cudaGetSymbolAddress((void**)&swf, g_swf);
    cudaGetSymbolAddress((void**)&proj, g_proj);

    cudaFuncSetAttribute(lif_gemm_hmma_kernel,
                         cudaFuncAttributeMaxDynamicSharedMemorySize, DSMEM);

    // digit splits (bf16 digit planes)
    split_kernel<<<M_, 256>>>(X, Xs, SX, sxf, (i64)M_ * I_);
    split_kernel<<<H_, 256>>>(W, Ws, SW, swf, (i64)H_ * I_);

    // bf16 HMMA GEMM with exact integer recombination
    dim3 ggrid(NT, MT);   // (32, 400)
    lif_gemm_hmma_kernel<<<ggrid, 256, DSMEM>>>(bias, proj);

    // LIF scan
    lif_scan_kernel<<<(B_ * H_ + 255) / 256, 256>>>(proj, out);
}

// round 10
// speedup vs baseline: 3.0820x; 1.3923x over previous
#include <cuda_runtime.h>
#include <cstdint>

typedef unsigned long long u64;
typedef long long           i64;

// ---------------------------------------------------------------------------
#define B_   256
#define T_   100
#define I_   2048
#define H_   2048
#define M_   (B_ * T_)      // 25600

#define BM   64
#define BN   64
#define MT   (M_ / BM)      // 400
#define NT   (H_ / BN)      // 32
#define NCHUNK (I_ / 64)    // 32 K-chunks of 64 bf16 elements (128 bytes/row)

#define PLANE 8192          // 64 rows x 128 B per digit slice
#define STAGE (8 * PLANE)   // 4 A planes + 4 B planes = 64 KiB
#define DSMEM (2 * STAGE)   // 128 KiB double buffered

#define NTHR 512            // 16 warps: 4 M-groups x 4 N-groups, warp tile m16n16

// Static device scratch (no allocations). Digits stored as bf16 bit patterns.
__device__ __align__(16) unsigned short g_Xs[4ll * M_ * I_];   // 400 MiB
__device__ __align__(16) unsigned short g_Ws[4ll * H_ * I_];   // 32 MiB
__device__ float g_sxf[M_];
__device__ float g_swf[H_];
__device__ float g_proj[(size_t)M_ * H_];                      // 200 MiB

// ---------------------------------------------------------------------------
// helpers (family-common PTX only)
// ---------------------------------------------------------------------------
__device__ __forceinline__ uint32_t smem_u32(const void* p) {
    uint32_t a;
    asm("{ .reg .u64 t; cvta.to.shared.u64 t, %1; cvt.u32.u64 %0, t; }" : "=r"(a) : "l"(p));
    return a;
}
__device__ __forceinline__ uint32_t sw128(uint32_t o) { return o ^ ((o >> 3) & 0x70); }

__device__ __forceinline__ void ldsm4(uint32_t& r0, uint32_t& r1, uint32_t& r2, uint32_t& r3,
                                      uint32_t a) {
    asm volatile("ldmatrix.sync.aligned.m8n8.x4.shared.b16 {%0,%1,%2,%3}, [%4];"
                 : "=r"(r0), "=r"(r1), "=r"(r2), "=r"(r3) : "r"(a));
}
__device__ __forceinline__ void cpa16(uint32_t d, const void* s) {
    asm volatile("cp.async.cg.shared.global [%0], [%1], 16;" :: "r"(d), "l"(s));
}
#define CP_COMMIT() asm volatile("cp.async.commit_group;")
#define CP_WAIT1()  asm volatile("cp.async.wait_group 1;")
#define CP_WAIT0()  asm volatile("cp.async.wait_group 0;")

// bf16 HMMA, fp32 accumulate (exact for our small integer digit values)
#define MMA(d, a, b) \
    asm volatile("mma.sync.aligned.m16n8k16.row.col.f32.bf16.bf16.f32 " \
                 "{%0,%1,%2,%3}, {%4,%5,%6,%7}, {%8,%9}, {%0,%1,%2,%3};" \
                 : "+f"((d)[0]), "+f"((d)[1]), "+f"((d)[2]), "+f"((d)[3]) \
                 : "r"((a)[0]), "r"((a)[1]), "r"((a)[2]), "r"((a)[3]), \
                   "r"((b)[0]), "r"((b)[1]))

// ---------------------------------------------------------------------------
// Split: per-row power-of-2 scale 2^e (> max|x|), 4 SIGNED base-256 digits
// via exact rint/EFT peel: u = (d0 + d1/2^8 + d2/2^16 + d3/2^24)/2^7 + eps,
// |d_i| <= 128 (exact in bf16), |eps| <= 2^-32. No offset corrections needed.
// ---------------------------------------------------------------------------
__global__ __launch_bounds__(256)
void split_kernel(const float* __restrict__ src, unsigned short* __restrict__ dst,
                  float* __restrict__ scl, i64 sstride)
{
    __shared__ float smax[256];
    __shared__ float s_inv;

    const int r = blockIdx.x;
    const int tid = threadIdx.x;
    const float* row = src + (size_t)r * I_;

    float mx = 0.0f;
    #pragma unroll
    for (int it = 0; it < I_ / 256; it++) mx = fmaxf(mx, fabsf(row[tid + it * 256]));
    smax[tid] = mx;
    __syncthreads();
    for (int s = 128; s > 0; s >>= 1) {
        if (tid < s) smax[tid] = fmaxf(smax[tid], smax[tid + s]);
        __syncthreads();
    }
    if (tid == 0) {
        int e = 0;
        if (smax[0] > 0.0f) frexpf(smax[0], &e);   // max = f*2^e, f in [0.5,1)
        s_inv = ldexpf(1.0f, -e);                  // |u| < 1
        scl[r] = ldexpf(1.0f, e - 19);             // scale / 2^19 (pairs to 2^-38)
    }
    __syncthreads();
    const float sinv = s_inv;

    #pragma unroll
    for (int it = 0; it < I_ / 256; it++) {
        int k = tid + it * 256;
        float u  = row[k] * sinv;                 // exact, |u| < 1
        float v0 = u * 128.0f;                    // exact, |v0| < 128
        float d0 = rintf(v0); float r0 = v0 - d0; // exact split, |r0| <= 0.5
        float v1 = r0 * 256.0f;
        float d1 = rintf(v1); float r1 = v1 - d1;
        float v2 = r1 * 256.0f;
        float d2 = rintf(v2); float r2 = v2 - d2;
        float d3 = rintf(r2 * 256.0f);            // |d3| <= 128, tail dropped

        i64 base = (i64)r * I_ + k;
        // exact fp32 -> bf16 bit truncation (values are integers |d|<=128)
        dst[0 * sstride + base] = (unsigned short)(__float_as_uint(d0) >> 16);
        dst[1 * sstride + base] = (unsigned short)(__float_as_uint(d1) >> 16);
        dst[2 * sstride + base] = (unsigned short)(__float_as_uint(d2) >> 16);
        dst[3 * sstride + base] = (unsigned short)(__float_as_uint(d3) >> 16);
    }
}

// ---------------------------------------------------------------------------
// GEMM: bf16 HMMA, 10 signed digit pairs (i+j<=3) into 4 fp32 accumulators
// (exact integers, |S|<2^24 guaranteed by folding every 128 K), folded into a
// signed i64 with weights 2^(24-8s). CTA 64x64, 16 warps (4Mx4N), warp m16n16,
// double-buffered cp.async chunks of 64 K-elements.
// ---------------------------------------------------------------------------
__global__ __launch_bounds__(NTHR, 1)
void lif_gemm_hmma_kernel(const float* __restrict__ bias, float* __restrict__ proj)
{
    extern __shared__ int8_t smem[];
    const uint32_t sb = smem_u32(smem);
    const int tid  = threadIdx.x;
    const int lane = tid & 31;
    const int wid  = tid >> 5;
    const int wm   = wid >> 2;    // 0..3 -> M group (16 rows)
    const int wn   = wid & 3;     // 0..3 -> N group (16 cols)
    const int bx = blockIdx.x;    // N tile
    const int by = blockIdx.y;    // M tile

    const int q  = lane >> 3;
    const int l7 = lane & 7;

    float D[4][2][4];   // [s][nt][e]
    i64   P[2][4];
    #pragma unroll
    for (int s = 0; s < 4; s++)
        #pragma unroll
        for (int nt = 0; nt < 2; nt++)
            #pragma unroll
            for (int e = 0; e < 4; e++) D[s][nt][e] = 0.0f;
    #pragma unroll
    for (int nt = 0; nt < 2; nt++)
        #pragma unroll
        for (int e = 0; e < 4; e++) P[nt][e] = 0ll;

#define LOAD_CHUNK(c) do {                                                        \
    uint32_t stg = sb + ((c) & 1) * STAGE;                                        \
    _Pragma("unroll")                                                             \
    for (int v = 0; v < 8; v++) {                                                 \
        int id = v * NTHR + tid;                                                  \
        int slice = (id >> 9) & 3;                                                \
        int idx = id & 511;                                                       \
        int row = idx >> 3, x = idx & 7;                                          \
        uint32_t dst = stg + ((id >> 11) ? 4 * PLANE : 0) + slice * PLANE         \
                     + sw128((uint32_t)(row * 128 + x * 16));                     \
        const unsigned short* src = (id >> 11)                                    \
            ? (g_Ws + (i64)slice * H_ * I_ + (i64)(bx * BN + row) * I_ + (c) * 64 + x * 8) \
            : (g_Xs + (i64)slice * M_ * I_ + (i64)(by * BM + row) * I_ + (c) * 64 + x * 8); \
        cpa16(dst, src);                                                          \
    }                                                                             \
    CP_COMMIT();                                                                  \
} while (0)

#define PP(i, j, s) {                                                             \
    MMA(D[s][0], A[i], Bt[j][0]);                                                 \
    MMA(D[s][1], A[i], Bt[j][1]);                                                 \
}

// chunk = 64 bf16 K-elems (128 B rows); ks selects a k16 slab (32 B).
#define COMPUTE_CHUNK(c) do {                                                     \
    uint32_t stg = sb + ((c) & 1) * STAGE;                                        \
    _Pragma("unroll")                                                             \
    for (int ks = 0; ks < 4; ks++) {                                              \
        uint32_t A[4][4];                                                         \
        _Pragma("unroll")                                                         \
        for (int sl = 0; sl < 4; sl++) {                                          \
            int row = wm * 16 + ((q & 1) << 3) + l7;                              \
            uint32_t ad = stg + sl * PLANE                                        \
                        + sw128((uint32_t)(row * 128 + ks * 32 + (q >> 1) * 16)); \
            ldsm4(A[sl][0], A[sl][1], A[sl][2], A[sl][3], ad);                    \
        }                                                                         \
        uint32_t Bt[4][2][2];                                                     \
        _Pragma("unroll")                                                         \
        for (int sl = 0; sl < 4; sl++) {                                          \
            int n = wn * 16 + ((q & 1) << 3) + l7;                                \
            uint32_t bd = stg + 4 * PLANE + sl * PLANE                            \
                        + sw128((uint32_t)(n * 128 + ks * 32 + (q >> 1) * 16));   \
            uint32_t r0, r1, r2, r3;                                              \
            ldsm4(r0, r1, r2, r3, bd);                                            \
            Bt[sl][0][0] = r0; Bt[sl][0][1] = r2;                                 \
            Bt[sl][1][0] = r1; Bt[sl][1][1] = r3;                                 \
        }                                                                         \
        PP(0,0,0)                                                                 \
        PP(0,1,1) PP(1,0,1)                                                       \
        PP(0,2,2) PP(1,1,2) PP(2,0,2)                                             \
        PP(0,3,3) PP(1,2,3) PP(2,1,3) PP(3,0,3)                                   \
    }                                                                             \
} while (0)

// Fold fp32 accumulators (exact integers, |S|<2^24) into signed i64,
// weights 2^(24-8s). V accumulates (u.v)*2^38 over the whole K range.
#define FOLD() do {                                                               \
    _Pragma("unroll")                                                             \
    for (int nt = 0; nt < 2; nt++) {                                              \
        _Pragma("unroll")                                                         \
        for (int e = 0; e < 4; e++) {                                             \
            P[nt][e] += ((i64)(int)D[0][nt][e] << 24)                             \
                      + ((i64)(int)D[1][nt][e] << 16)                             \
                      + ((i64)(int)D[2][nt][e] << 8)                              \
                      +  (i64)(int)D[3][nt][e];                                   \
            _Pragma("unroll")                                                     \
            for (int s = 0; s < 4; s++) D[s][nt][e] = 0.0f;                       \
        }                                                                         \
    }                                                                             \
} while (0)

    LOAD_CHUNK(0);
    #pragma unroll 1
    for (int c = 0; c < NCHUNK; c++) {
        if (c + 1 < NCHUNK) {
            LOAD_CHUNK(c + 1);
            CP_WAIT1();
        } else {
            CP_WAIT0();
        }
        __syncthreads();
        COMPUTE_CHUNK(c);
        __syncthreads();
        if (c & 1) FOLD();      // every 128 K: 4 pairs * 128 * 2^14 = 2^23 < 2^24
    }

    // ---- epilogue: proj = P * 2^-38 * 2^(ex+ew) + bias, one rounding ----
    const int mrow0 = by * BM + wm * 16 + (lane >> 2);
    const int col0  = bx * BN + wn * 16 + 2 * (lane & 3);

    #pragma unroll
    for (int half = 0; half < 2; half++) {
        int m = mrow0 + 8 * half;
        double sx = (double)g_sxf[m];            // 2^(ex-19)
        float* orow = proj + (size_t)m * H_ + col0;
        #pragma unroll
        for (int nt = 0; nt < 2; nt++) {
            float v[2];
            #pragma unroll
            for (int dj = 0; dj < 2; dj++) {
                int h = col0 + 8 * nt + dj;
                int e = 2 * half + dj;
                double sc = sx * (double)g_swf[h];   // 2^(ex+ew-38), exact
                v[dj] = (float)((double)P[nt][e] * sc + (double)bias[h]);
            }
            *(float2*)(orow + 8 * nt) = make_float2(v[0], v[1]);
        }
    }
#undef LOAD_CHUNK
#undef COMPUTE_CHUNK
#undef PP
#undef FOLD
}

// ---------------------------------------------------------------------------
// LIF scan (measured ~67us, DRAM ~71%)
// ---------------------------------------------------------------------------
__global__ __launch_bounds__(256)
void lif_scan_kernel(const float* __restrict__ proj, float* __restrict__ out)
{
    int idx = blockIdx.x * blockDim.x + threadIdx.x;
    if (idx >= B_ * H_) return;
    int b = idx / H_;
    int h = idx % H_;
    const size_t base = (size_t)b * T_ * H_ + h;
    float hs = 0.0f;
    #pragma unroll 4
    for (int t = 0; t < T_; t++) {
        float p = proj[base + (size_t)t * H_];
        hs = __fadd_rn(__fmul_rn(0.9f, hs), p);
        float sp = (hs >= 1.0f) ? 1.0f : 0.0f;
        out[base + (size_t)t * H_] = sp;
        hs = __fmul_rn(hs, __fsub_rn(1.0f, sp));
    }
    out[(size_t)B_ * T_ * H_ + (size_t)b * H_ + h] = hs;
}

// ---------------------------------------------------------------------------
extern "C" void kernel_launch(void* const* d_in, const int* in_sizes, int n_in,
                              void* d_out, int out_size)
{
    const float* X    = (const float*)d_in[0];
    const float* W    = (const float*)d_in[1];
    const float* bias = (const float*)d_in[2];
    float* out = (float*)d_out;

    unsigned short *Xs, *Ws;
    float *sxf, *swf, *proj;
    cudaGetSymbolAddress((void**)&Xs, g_Xs);
    cudaGetSymbolAddress((void**)&Ws, g_Ws);
    cudaGetSymbolAddress((void**)&sxf, g_sxf);
    cudaGetSymbolAddress((void**)&swf, g_swf);
    cudaGetSymbolAddress((void**)&proj, g_proj);

    cudaFuncSetAttribute(lif_gemm_hmma_kernel,
                         cudaFuncAttributeMaxDynamicSharedMemorySize, DSMEM);

    // signed-digit splits (bf16 digit planes)
    split_kernel<<<M_, 256>>>(X, Xs, sxf, (i64)M_ * I_);
    split_kernel<<<H_, 256>>>(W, Ws, swf, (i64)H_ * I_);

    // bf16 HMMA GEMM, 10 pairs, exact integer recombination
    dim3 ggrid(NT, MT);   // (32, 400): bx fastest -> X tiles shared in L2
    lif_gemm_hmma_kernel<<<ggrid, NTHR, DSMEM>>>(bias, proj);

    // LIF scan
    lif_scan_kernel<<<(B_ * H_ + 255) / 256, 256>>>(proj, out);
}

// round 11
// speedup vs baseline: 3.5189x; 1.1418x over previous
#include <cuda_runtime.h>
#include <cstdint>

typedef unsigned long long u64;
typedef long long           i64;

// ---------------------------------------------------------------------------
#define B_   256
#define T_   100
#define I_   2048
#define H_   2048
#define M_   (B_ * T_)      // 25600

#define BM   64
#define BN   64
#define MT   (M_ / BM)      // 400
#define NT   (H_ / BN)      // 32
#define NCHUNK (I_ / 64)    // 32 K-chunks of 64 bf16 elements (128 bytes/row)

#define NSLICE 3            // base-512 digits: 3 slices per operand
#define PLANE 8192          // 64 rows x 128 B per digit slice
#define STAGE (2 * NSLICE * PLANE)   // 3 A planes + 3 B planes = 48 KiB
#define DSMEM (2 * STAGE)            // 96 KiB double buffered

#define NTHR 512            // 16 warps: 4 M-groups x 4 N-groups, warp tile m16n16

// Static device scratch (no allocations). Digits stored as bf16 bit patterns.
__device__ __align__(16) unsigned short g_Xs[(i64)NSLICE * M_ * I_];   // 300 MiB
__device__ __align__(16) unsigned short g_Ws[(i64)NSLICE * H_ * I_];   // 24 MiB
__device__ float g_sxf[M_];
__device__ float g_swf[H_];
__device__ float g_proj[(size_t)M_ * H_];                              // 200 MiB

// ---------------------------------------------------------------------------
// helpers (family-common PTX only)
// ---------------------------------------------------------------------------
__device__ __forceinline__ uint32_t smem_u32(const void* p) {
    uint32_t a;
    asm("{ .reg .u64 t; cvta.to.shared.u64 t, %1; cvt.u32.u64 %0, t; }" : "=r"(a) : "l"(p));
    return a;
}
__device__ __forceinline__ uint32_t sw128(uint32_t o) { return o ^ ((o >> 3) & 0x70); }

__device__ __forceinline__ void ldsm4(uint32_t& r0, uint32_t& r1, uint32_t& r2, uint32_t& r3,
                                      uint32_t a) {
    asm volatile("ldmatrix.sync.aligned.m8n8.x4.shared.b16 {%0,%1,%2,%3}, [%4];"
                 : "=r"(r0), "=r"(r1), "=r"(r2), "=r"(r3) : "r"(a));
}
__device__ __forceinline__ void cpa16(uint32_t d, const void* s) {
    asm volatile("cp.async.cg.shared.global [%0], [%1], 16;" :: "r"(d), "l"(s));
}
#define CP_COMMIT() asm volatile("cp.async.commit_group;")
#define CP_WAIT1()  asm volatile("cp.async.wait_group 1;")
#define CP_WAIT0()  asm volatile("cp.async.wait_group 0;")

// bf16 HMMA, fp32 accumulate (exact for our small integer digit values)
#define MMA(d, a, b) \
    asm volatile("mma.sync.aligned.m16n8k16.row.col.f32.bf16.bf16.f32 " \
                 "{%0,%1,%2,%3}, {%4,%5,%6,%7}, {%8,%9}, {%0,%1,%2,%3};" \
                 : "+f"((d)[0]), "+f"((d)[1]), "+f"((d)[2]), "+f"((d)[3]) \
                 : "r"((a)[0]), "r"((a)[1]), "r"((a)[2]), "r"((a)[3]), \
                   "r"((b)[0]), "r"((b)[1]))

// ---------------------------------------------------------------------------
// Split: per-row power-of-2 scale 2^e (> max|x|), 3 SIGNED base-512 digits
// via exact rint peel: u = d0*2^-8 + d1*2^-17 + d2*2^-26 + r2*2^-26, |r2|<=0.5,
// |d_i| <= 256 (exact in bf16: 8 significand bits). Tail 2^-27.
// ---------------------------------------------------------------------------
__global__ __launch_bounds__(256)
void split_kernel(const float* __restrict__ src, unsigned short* __restrict__ dst,
                  float* __restrict__ scl, i64 sstride, int sbias)
{
    __shared__ float smax[256];
    __shared__ float s_inv;

    const int r = blockIdx.x;
    const int tid = threadIdx.x;
    const float* row = src + (size_t)r * I_;

    float mx = 0.0f;
    #pragma unroll
    for (int it = 0; it < I_ / 256; it++) mx = fmaxf(mx, fabsf(row[tid + it * 256]));
    smax[tid] = mx;
    __syncthreads();
    for (int s = 128; s > 0; s >>= 1) {
        if (tid < s) smax[tid] = fmaxf(smax[tid], smax[tid + s]);
        __syncthreads();
    }
    if (tid == 0) {
        int e = 0;
        if (smax[0] > 0.0f) frexpf(smax[0], &e);   // max = f*2^e, f in [0.5,1)
        s_inv = ldexpf(1.0f, -e);                  // |u| < 1
        scl[r] = ldexpf(1.0f, e + sbias);          // sbias: -21 (X), -22 (W)
    }
    __syncthreads();
    const float sinv = s_inv;

    #pragma unroll
    for (int it = 0; it < I_ / 256; it++) {
        int k = tid + it * 256;
        float u  = row[k] * sinv;                 // exact, |u| < 1
        float v0 = u * 256.0f;                    // exact, |v0| < 256
        float d0 = rintf(v0); float r0 = v0 - d0; // exact, |d0|<=256, |r0|<=0.5
        float v1 = r0 * 512.0f;
        float d1 = rintf(v1); float r1 = v1 - d1; // |d1|<=256
        float d2 = rintf(r1 * 512.0f);            // |d2|<=256, tail dropped

        i64 base = (i64)r * I_ + k;
        // exact fp32 -> bf16 bit truncation (values are integers |d|<=256)
        dst[0 * sstride + base] = (unsigned short)(__float_as_uint(d0) >> 16);
        dst[1 * sstride + base] = (unsigned short)(__float_as_uint(d1) >> 16);
        dst[2 * sstride + base] = (unsigned short)(__float_as_uint(d2) >> 16);
    }
}

// ---------------------------------------------------------------------------
// GEMM: bf16 HMMA, 8 digit pairs over 3x3 base-512 digits:
//   s=0:(0,0)  s=1:(0,1)(1,0)  s=2:(0,2)(1,1)(2,0)  s=3:(1,2)(2,1)
// 4 fp32 accumulators (exact integers; fold every 64-K chunk keeps |S|<2^24),
// folded into signed i64 with weights 2^(27-9s). CTA 64x64, 16 warps (4Mx4N),
// warp tile m16n16, double-buffered cp.async chunks.
// ---------------------------------------------------------------------------
__global__ __launch_bounds__(NTHR, 1)
void lif_gemm_hmma_kernel(const float* __restrict__ bias, float* __restrict__ proj)
{
    extern __shared__ int8_t smem[];
    const uint32_t sb = smem_u32(smem);
    const int tid  = threadIdx.x;
    const int lane = tid & 31;
    const int wid  = tid >> 5;
    const int wm   = wid >> 2;    // 0..3 -> M group (16 rows)
    const int wn   = wid & 3;     // 0..3 -> N group (16 cols)
    const int bx = blockIdx.x;    // N tile
    const int by = blockIdx.y;    // M tile

    const int q  = lane >> 3;
    const int l7 = lane & 7;

    float D[4][2][4];   // [s][nt][e]
    i64   P[2][4];
    #pragma unroll
    for (int s = 0; s < 4; s++)
        #pragma unroll
        for (int nt = 0; nt < 2; nt++)
            #pragma unroll
            for (int e = 0; e < 4; e++) D[s][nt][e] = 0.0f;
    #pragma unroll
    for (int nt = 0; nt < 2; nt++)
        #pragma unroll
        for (int e = 0; e < 4; e++) P[nt][e] = 0ll;

// 6 planes x 512 vec16 = 3072 cp.async per chunk; 6 per thread at 512 thr.
#define LOAD_CHUNK(c) do {                                                        \
    uint32_t stg = sb + ((c) & 1) * STAGE;                                        \
    _Pragma("unroll")                                                             \
    for (int v = 0; v < 6; v++) {                                                 \
        int id = v * NTHR + tid;                                                  \
        int plane = id >> 9;          /* 0..5: 0-2 A slices, 3-5 B slices */      \
        int idx = id & 511;                                                       \
        int row = idx >> 3, x = idx & 7;                                          \
        uint32_t dst = stg + plane * PLANE                                        \
                     + sw128((uint32_t)(row * 128 + x * 16));                     \
        const unsigned short* src = (plane >= NSLICE)                             \
            ? (g_Ws + (i64)(plane - NSLICE) * H_ * I_ + (i64)(bx * BN + row) * I_ + (c) * 64 + x * 8) \
            : (g_Xs + (i64)plane * M_ * I_ + (i64)(by * BM + row) * I_ + (c) * 64 + x * 8); \
        cpa16(dst, src);                                                          \
    }                                                                             \
    CP_COMMIT();                                                                  \
} while (0)

#define PP(i, j, s) {                                                             \
    MMA(D[s][0], A[i], Bt[j][0]);                                                 \
    MMA(D[s][1], A[i], Bt[j][1]);                                                 \
}

// chunk = 64 bf16 K-elems (128 B rows); ks selects a k16 slab (32 B).
// Pair order interleaves s so no two consecutive mma share an accumulator.
#define COMPUTE_CHUNK(c) do {                                                     \
    uint32_t stg = sb + ((c) & 1) * STAGE;                                        \
    _Pragma("unroll")                                                             \
    for (int ks = 0; ks < 4; ks++) {                                              \
        uint32_t A[NSLICE][4];                                                    \
        _Pragma("unroll")                                                         \
        for (int sl = 0; sl < NSLICE; sl++) {                                     \
            int row = wm * 16 + ((q & 1) << 3) + l7;                              \
            uint32_t ad = stg + sl * PLANE                                        \
                        + sw128((uint32_t)(row * 128 + ks * 32 + (q >> 1) * 16)); \
            ldsm4(A[sl][0], A[sl][1], A[sl][2], A[sl][3], ad);                    \
        }                                                                         \
        uint32_t Bt[NSLICE][2][2];                                                \
        _Pragma("unroll")                                                         \
        for (int sl = 0; sl < NSLICE; sl++) {                                     \
            int n = wn * 16 + ((q & 1) << 3) + l7;                                \
            uint32_t bd = stg + NSLICE * PLANE + sl * PLANE                       \
                        + sw128((uint32_t)(n * 128 + ks * 32 + (q >> 1) * 16));   \
            uint32_t r0, r1, r2, r3;                                              \
            ldsm4(r0, r1, r2, r3, bd);                                            \
            Bt[sl][0][0] = r0; Bt[sl][0][1] = r2;                                 \
            Bt[sl][1][0] = r1; Bt[sl][1][1] = r3;                                 \
        }                                                                         \
        PP(0,0,0) PP(0,1,1) PP(0,2,2) PP(1,0,1)                                   \
        PP(1,1,2) PP(1,2,3) PP(2,0,2) PP(2,1,3)                                   \
    }                                                                             \
} while (0)

// Fold fp32 accumulators (exact integers, |S| <= 3*64*2^16 < 2^24) into i64,
// weights 2^(27-9s). P accumulates (u.v)*2^43 over the whole K range.
#define FOLD() do {                                                               \
    _Pragma("unroll")                                                             \
    for (int nt = 0; nt < 2; nt++) {                                              \
        _Pragma("unroll")                                                         \
        for (int e = 0; e < 4; e++) {                                             \
            P[nt][e] += ((i64)(int)D[0][nt][e] << 27)                             \
                      + ((i64)(int)D[1][nt][e] << 18)                             \
                      + ((i64)(int)D[2][nt][e] << 9)                              \
                      +  (i64)(int)D[3][nt][e];                                   \
            _Pragma("unroll")                                                     \
            for (int s = 0; s < 4; s++) D[s][nt][e] = 0.0f;                       \
        }                                                                         \
    }                                                                             \
} while (0)

    LOAD_CHUNK(0);
    #pragma unroll 1
    for (int c = 0; c < NCHUNK; c++) {
        if (c + 1 < NCHUNK) {
            LOAD_CHUNK(c + 1);
            CP_WAIT1();
        } else {
            CP_WAIT0();
        }
        __syncthreads();
        COMPUTE_CHUNK(c);
        __syncthreads();
        FOLD();   // every 64 K: worst s has 3 pairs * 64 * 2^16 = 1.26e7 < 2^24
    }

    // ---- epilogue: proj = P * 2^(ex+ew-43) + bias, one rounding ----
    const int mrow0 = by * BM + wm * 16 + (lane >> 2);
    const int col0  = bx * BN + wn * 16 + 2 * (lane & 3);

    #pragma unroll
    for (int half = 0; half < 2; half++) {
        int m = mrow0 + 8 * half;
        double sx = (double)g_sxf[m];            // 2^(ex-21)
        float* orow = proj + (size_t)m * H_ + col0;
        #pragma unroll
        for (int nt = 0; nt < 2; nt++) {
            float v[2];
            #pragma unroll
            for (int dj = 0; dj < 2; dj++) {
                int h = col0 + 8 * nt + dj;
                int e = 2 * half + dj;
                double sc = sx * (double)g_swf[h];   // 2^(ex+ew-43), exact
                v[dj] = (float)((double)P[nt][e] * sc + (double)bias[h]);
            }
            *(float2*)(orow + 8 * nt) = make_float2(v[0], v[1]);
        }
    }
#undef LOAD_CHUNK
#undef COMPUTE_CHUNK
#undef PP
#undef FOLD
}

// ---------------------------------------------------------------------------
// LIF scan (measured ~66us, DRAM ~72%)
// ---------------------------------------------------------------------------
__global__ __launch_bounds__(256)
void lif_scan_kernel(const float* __restrict__ proj, float* __restrict__ out)
{
    int idx = blockIdx.x * blockDim.x + threadIdx.x;
    if (idx >= B_ * H_) return;
    int b = idx / H_;
    int h = idx % H_;
    const size_t base = (size_t)b * T_ * H_ + h;
    float hs = 0.0f;
    #pragma unroll 4
    for (int t = 0; t < T_; t++) {
        float p = proj[base + (size_t)t * H_];
        hs = __fadd_rn(__fmul_rn(0.9f, hs), p);
        float sp = (hs >= 1.0f) ? 1.0f : 0.0f;
        out[base + (size_t)t * H_] = sp;
        hs = __fmul_rn(hs, __fsub_rn(1.0f, sp));
    }
    out[(size_t)B_ * T_ * H_ + (size_t)b * H_ + h] = hs;
}

// ---------------------------------------------------------------------------
extern "C" void kernel_launch(void* const* d_in, const int* in_sizes, int n_in,
                              void* d_out, int out_size)
{
    const float* X    = (const float*)d_in[0];
    const float* W    = (const float*)d_in[1];
    const float* bias = (const float*)d_in[2];
    float* out = (float*)d_out;

    unsigned short *Xs, *Ws;
    float *sxf, *swf, *proj;
    cudaGetSymbolAddress((void**)&Xs, g_Xs);
    cudaGetSymbolAddress((void**)&Ws, g_Ws);
    cudaGetSymbolAddress((void**)&sxf, g_sxf);
    cudaGetSymbolAddress((void**)&swf, g_swf);
    cudaGetSymbolAddress((void**)&proj, g_proj);

    cudaFuncSetAttribute(lif_gemm_hmma_kernel,
                         cudaFuncAttributeMaxDynamicSharedMemorySize, DSMEM);

    // signed base-512 digit splits (3 bf16 planes per operand)
    split_kernel<<<M_, 256>>>(X, Xs, sxf, (i64)M_ * I_, -21);
    split_kernel<<<H_, 256>>>(W, Ws, swf, (i64)H_ * I_, -22);

    // bf16 HMMA GEMM, 8 pairs, exact integer recombination
    dim3 ggrid(NT, MT);   // (32, 400): bx fastest -> X tiles shared in L2
    lif_gemm_hmma_kernel<<<ggrid, NTHR, DSMEM>>>(bias, proj);

    // LIF scan
    lif_scan_kernel<<<(B_ * H_ + 255) / 256, 256>>>(proj, out);
}

// round 12
// speedup vs baseline: 3.9867x; 1.1329x over previous
#include <cuda_runtime.h>
#include <cuda_fp16.h>
#include <cstdint>

typedef unsigned long long u64;
typedef long long           i64;

// ---------------------------------------------------------------------------
#define B_   256
#define T_   100
#define I_   2048
#define H_   2048
#define M_   (B_ * T_)      // 25600

#define BM   64
#define BN   64
#define MT   (M_ / BM)      // 400
#define NT   (H_ / BN)      // 32
#define NCHUNK (I_ / 64)    // 32 K-chunks of 64 fp16 elements (128 bytes/row)

#define NSLICE 3            // base-1024 digits: 3 slices per operand
#define PLANE 8192          // 64 rows x 128 B per digit slice
#define STAGE (2 * NSLICE * PLANE)   // 3 A planes + 3 B planes = 48 KiB
#define DSMEM (2 * STAGE)            // 96 KiB double buffered

#define NTHR 512            // 16 warps: 4 M-groups x 4 N-groups, warp tile m16n16

// Static device scratch (no allocations). Digits stored as fp16 bit patterns.
__device__ __align__(16) unsigned short g_Xs[(i64)NSLICE * M_ * I_];   // 300 MiB
__device__ __align__(16) unsigned short g_Ws[(i64)NSLICE * H_ * I_];   // 24 MiB
__device__ float g_sxf[M_];
__device__ float g_swf[H_];
__device__ float g_proj[(size_t)M_ * H_];                              // 200 MiB

// ---------------------------------------------------------------------------
// helpers (family-common PTX only)
// ---------------------------------------------------------------------------
__device__ __forceinline__ uint32_t smem_u32(const void* p) {
    uint32_t a;
    asm("{ .reg .u64 t; cvta.to.shared.u64 t, %1; cvt.u32.u64 %0, t; }" : "=r"(a) : "l"(p));
    return a;
}
__device__ __forceinline__ uint32_t sw128(uint32_t o) { return o ^ ((o >> 3) & 0x70); }

__device__ __forceinline__ void ldsm4(uint32_t& r0, uint32_t& r1, uint32_t& r2, uint32_t& r3,
                                      uint32_t a) {
    asm volatile("ldmatrix.sync.aligned.m8n8.x4.shared.b16 {%0,%1,%2,%3}, [%4];"
                 : "=r"(r0), "=r"(r1), "=r"(r2), "=r"(r3) : "r"(a));
}
__device__ __forceinline__ void cpa16(uint32_t d, const void* s) {
    asm volatile("cp.async.cg.shared.global [%0], [%1], 16;" :: "r"(d), "l"(s));
}
#define CP_COMMIT() asm volatile("cp.async.commit_group;")
#define CP_WAIT1()  asm volatile("cp.async.wait_group 1;")
#define CP_WAIT0()  asm volatile("cp.async.wait_group 0;")

// fp16 HMMA, fp32 accumulate (exact: integer digit products, |S| <= 2^24)
#define MMA(d, a, b) \
    asm volatile("mma.sync.aligned.m16n8k16.row.col.f32.f16.f16.f32 " \
                 "{%0,%1,%2,%3}, {%4,%5,%6,%7}, {%8,%9}, {%0,%1,%2,%3};" \
                 : "+f"((d)[0]), "+f"((d)[1]), "+f"((d)[2]), "+f"((d)[3]) \
                 : "r"((a)[0]), "r"((a)[1]), "r"((a)[2]), "r"((a)[3]), \
                   "r"((b)[0]), "r"((b)[1]))

// ---------------------------------------------------------------------------
// Split: per-row power-of-2 scale 2^e (> max|x|), 3 SIGNED base-1024 digits:
// u = d0*2^-9 + d1*2^-19 + d2*2^-29 + r2*2^-30, |d_i| <= 512 (exact in fp16,
// 11 significand bits), all peel steps exact fp32 EFT splits. Tail 2^-30.
// ---------------------------------------------------------------------------
__global__ __launch_bounds__(256)
void split_kernel(const float* __restrict__ src, unsigned short* __restrict__ dst,
                  float* __restrict__ scl, i64 sstride)
{
    __shared__ float smax[256];
    __shared__ float s_inv;

    const int r = blockIdx.x;
    const int tid = threadIdx.x;
    const float* row = src + (size_t)r * I_;

    float mx = 0.0f;
    #pragma unroll
    for (int it = 0; it < I_ / 256; it++) mx = fmaxf(mx, fabsf(row[tid + it * 256]));
    smax[tid] = mx;
    __syncthreads();
    for (int s = 128; s > 0; s >>= 1) {
        if (tid < s) smax[tid] = fmaxf(smax[tid], smax[tid + s]);
        __syncthreads();
    }
    if (tid == 0) {
        int e = 0;
        if (smax[0] > 0.0f) frexpf(smax[0], &e);   // max = f*2^e, f in [0.5,1)
        s_inv = ldexpf(1.0f, -e);                  // |u| < 1
        scl[r] = ldexpf(1.0f, e - 24);             // pair scale: 2^(ex-24)*2^(ew-24) = 2^(ex+ew-48)
    }
    __syncthreads();
    const float sinv = s_inv;

    #pragma unroll
    for (int it = 0; it < I_ / 256; it++) {
        int k = tid + it * 256;
        float u  = row[k] * sinv;                 // exact, |u| < 1
        float v0 = u * 512.0f;                    // exact, |v0| < 512
        float d0 = rintf(v0);  float r0 = v0 - d0;  // exact, |d0|<=512, |r0|<=0.5
        float v1 = r0 * 1024.0f;
        float d1 = rintf(v1);  float r1 = v1 - d1;  // |d1|<=512
        float d2 = rintf(r1 * 1024.0f);             // |d2|<=512, tail 2^-30 dropped

        i64 base = (i64)r * I_ + k;
        // fp32 -> fp16 exact for integers |d|<=512
        dst[0 * sstride + base] = __half_as_ushort(__float2half_rn(d0));
        dst[1 * sstride + base] = __half_as_ushort(__float2half_rn(d1));
        dst[2 * sstride + base] = __half_as_ushort(__float2half_rn(d2));
    }
}

// ---------------------------------------------------------------------------
// GEMM: fp16 HMMA, 6 digit pairs (i+j<=2), ONE fp32 accumulator per pair
// (exact: |S| <= 64 * 2^18 = 2^24 per chunk), folded into signed i64 each
// chunk with weights 2^(30-10s). CTA 64x64, 16 warps (4Mx4N), warp m16n16,
// double-buffered cp.async chunks of 64 K-elements.
// Pair -> accumulator: (0,0)->0 (0,1)->1 (1,0)->2 (0,2)->3 (1,1)->4 (2,0)->5
// ---------------------------------------------------------------------------
__global__ __launch_bounds__(NTHR, 1)
void lif_gemm_hmma_kernel(const float* __restrict__ bias, float* __restrict__ proj)
{
    extern __shared__ int8_t smem[];
    const uint32_t sb = smem_u32(smem);
    const int tid  = threadIdx.x;
    const int lane = tid & 31;
    const int wid  = tid >> 5;
    const int wm   = wid >> 2;    // 0..3 -> M group (16 rows)
    const int wn   = wid & 3;     // 0..3 -> N group (16 cols)
    const int bx = blockIdx.x;    // N tile
    const int by = blockIdx.y;    // M tile

    const int q  = lane >> 3;
    const int l7 = lane & 7;

    float D[6][2][4];   // [pair][nt][e]
    i64   P[2][4];
    #pragma unroll
    for (int s = 0; s < 6; s++)
        #pragma unroll
        for (int nt = 0; nt < 2; nt++)
            #pragma unroll
            for (int e = 0; e < 4; e++) D[s][nt][e] = 0.0f;
    #pragma unroll
    for (int nt = 0; nt < 2; nt++)
        #pragma unroll
        for (int e = 0; e < 4; e++) P[nt][e] = 0ll;

// 6 planes x 512 vec16 = 3072 cp.async per chunk; 6 per thread at 512 thr.
#define LOAD_CHUNK(c) do {                                                        \
    uint32_t stg = sb + ((c) & 1) * STAGE;                                        \
    _Pragma("unroll")                                                             \
    for (int v = 0; v < 6; v++) {                                                 \
        int id = v * NTHR + tid;                                                  \
        int plane = id >> 9;          /* 0..5: 0-2 A slices, 3-5 B slices */      \
        int idx = id & 511;                                                       \
        int row = idx >> 3, x = idx & 7;                                          \
        uint32_t dst = stg + plane * PLANE                                        \
                     + sw128((uint32_t)(row * 128 + x * 16));                     \
        const unsigned short* src = (plane >= NSLICE)                             \
            ? (g_Ws + (i64)(plane - NSLICE) * H_ * I_ + (i64)(bx * BN + row) * I_ + (c) * 64 + x * 8) \
            : (g_Xs + (i64)plane * M_ * I_ + (i64)(by * BM + row) * I_ + (c) * 64 + x * 8); \
        cpa16(dst, src);                                                          \
    }                                                                             \
    CP_COMMIT();                                                                  \
} while (0)

#define PP(i, j, d) {                                                             \
    MMA(D[d][0], A[i], Bt[j][0]);                                                 \
    MMA(D[d][1], A[i], Bt[j][1]);                                                 \
}

// chunk = 64 fp16 K-elems (128 B rows); ks selects a k16 slab (32 B).
// All 6 pairs use distinct accumulators: zero mma->mma dependencies per step.
#define COMPUTE_CHUNK(c) do {                                                     \
    uint32_t stg = sb + ((c) & 1) * STAGE;                                        \
    _Pragma("unroll")                                                             \
    for (int ks = 0; ks < 4; ks++) {                                              \
        uint32_t A[NSLICE][4];                                                    \
        _Pragma("unroll")                                                         \
        for (int sl = 0; sl < NSLICE; sl++) {                                     \
            int row = wm * 16 + ((q & 1) << 3) + l7;                              \
            uint32_t ad = stg + sl * PLANE                                        \
                        + sw128((uint32_t)(row * 128 + ks * 32 + (q >> 1) * 16)); \
            ldsm4(A[sl][0], A[sl][1], A[sl][2], A[sl][3], ad);                    \
        }                                                                         \
        uint32_t Bt[NSLICE][2][2];                                                \
        _Pragma("unroll")                                                         \
        for (int sl = 0; sl < NSLICE; sl++) {                                     \
            int n = wn * 16 + ((q & 1) << 3) + l7;                                \
            uint32_t bd = stg + NSLICE * PLANE + sl * PLANE                       \
                        + sw128((uint32_t)(n * 128 + ks * 32 + (q >> 1) * 16));   \
            uint32_t r0, r1, r2, r3;                                              \
            ldsm4(r0, r1, r2, r3, bd);                                            \
            Bt[sl][0][0] = r0; Bt[sl][0][1] = r2;                                 \
            Bt[sl][1][0] = r1; Bt[sl][1][1] = r3;                                 \
        }                                                                         \
        PP(0,0,0) PP(0,1,1) PP(1,0,2) PP(0,2,3) PP(1,1,4) PP(2,0,5)               \
    }                                                                             \
} while (0)

// Fold per-pair fp32 accumulators (exact integers <= 2^24) into signed i64:
// u*v*2^48 = S0*2^30 + (S01+S10)*2^20 + (S02+S11+S20)*2^10 (+dropped 2^-30 tail)
#define FOLD() do {                                                               \
    _Pragma("unroll")                                                             \
    for (int nt = 0; nt < 2; nt++) {                                              \
        _Pragma("unroll")                                                         \
        for (int e = 0; e < 4; e++) {                                             \
            P[nt][e] += ((i64)(int)D[0][nt][e] << 30)                             \
                      + ((i64)((int)D[1][nt][e] + (int)D[2][nt][e]) << 20)        \
                      + ((i64)((int)D[3][nt][e] + (int)D[4][nt][e]                \
                             + (int)D[5][nt][e]) << 10);                          \
            _Pragma("unroll")                                                     \
            for (int s = 0; s < 6; s++) D[s][nt][e] = 0.0f;                       \
        }                                                                         \
    }                                                                             \
} while (0)

    LOAD_CHUNK(0);
    #pragma unroll 1
    for (int c = 0; c < NCHUNK; c++) {
        if (c + 1 < NCHUNK) {
            LOAD_CHUNK(c + 1);
            CP_WAIT1();
        } else {
            CP_WAIT0();
        }
        __syncthreads();
        COMPUTE_CHUNK(c);
        __syncthreads();
        FOLD();   // per chunk: |S| <= 64 * 512 * 512 = 2^24, integer-exact in fp32
    }

    // ---- epilogue: proj = P * 2^(ex+ew-48) + bias, one rounding ----
    const int mrow0 = by * BM + wm * 16 + (lane >> 2);
    const int col0  = bx * BN + wn * 16 + 2 * (lane & 3);

    #pragma unroll
    for (int half = 0; half < 2; half++) {
        int m = mrow0 + 8 * half;
        double sx = (double)g_sxf[m];            // 2^(ex-24)
        float* orow = proj + (size_t)m * H_ + col0;
        #pragma unroll
        for (int nt = 0; nt < 2; nt++) {
            float v[2];
            #pragma unroll
            for (int dj = 0; dj < 2; dj++) {
                int h = col0 + 8 * nt + dj;
                int e = 2 * half + dj;
                double sc = sx * (double)g_swf[h];   // 2^(ex+ew-48), exact
                v[dj] = (float)((double)P[nt][e] * sc + (double)bias[h]);
            }
            *(float2*)(orow + 8 * nt) = make_float2(v[0], v[1]);
        }
    }
#undef LOAD_CHUNK
#undef COMPUTE_CHUNK
#undef PP
#undef FOLD
}

// ---------------------------------------------------------------------------
// LIF scan (measured ~65us, DRAM ~72%)
// ---------------------------------------------------------------------------
__global__ __launch_bounds__(256)
void lif_scan_kernel(const float* __restrict__ proj, float* __restrict__ out)
{
    int idx = blockIdx.x * blockDim.x + threadIdx.x;
    if (idx >= B_ * H_) return;
    int b = idx / H_;
    int h = idx % H_;
    const size_t base = (size_t)b * T_ * H_ + h;
    float hs = 0.0f;
    #pragma unroll 4
    for (int t = 0; t < T_; t++) {
        float p = proj[base + (size_t)t * H_];
        hs = __fadd_rn(__fmul_rn(0.9f, hs), p);
        float sp = (hs >= 1.0f) ? 1.0f : 0.0f;
        out[base + (size_t)t * H_] = sp;
        hs = __fmul_rn(hs, __fsub_rn(1.0f, sp));
    }
    out[(size_t)B_ * T_ * H_ + (size_t)b * H_ + h] = hs;
}

// ---------------------------------------------------------------------------
extern "C" void kernel_launch(void* const* d_in, const int* in_sizes, int n_in,
                              void* d_out, int out_size)
{
    const float* X    = (const float*)d_in[0];
    const float* W    = (const float*)d_in[1];
    const float* bias = (const float*)d_in[2];
    float* out = (float*)d_out;

    unsigned short *Xs, *Ws;
    float *sxf, *swf, *proj;
    cudaGetSymbolAddress((void**)&Xs, g_Xs);
    cudaGetSymbolAddress((void**)&Ws, g_Ws);
    cudaGetSymbolAddress((void**)&sxf, g_sxf);
    cudaGetSymbolAddress((void**)&swf, g_swf);
    cudaGetSymbolAddress((void**)&proj, g_proj);

    cudaFuncSetAttribute(lif_gemm_hmma_kernel,
                         cudaFuncAttributeMaxDynamicSharedMemorySize, DSMEM);

    // signed base-1024 digit splits (3 fp16 planes per operand)
    split_kernel<<<M_, 256>>>(X, Xs, sxf, (i64)M_ * I_);
    split_kernel<<<H_, 256>>>(W, Ws, swf, (i64)H_ * I_);

    // fp16 HMMA GEMM, 6 pairs, exact integer recombination
    dim3 ggrid(NT, MT);   // (32, 400): bx fastest -> X tiles shared in L2
    lif_gemm_hmma_kernel<<<ggrid, NTHR, DSMEM>>>(bias, proj);

    // LIF scan
    lif_scan_kernel<<<(B_ * H_ + 255) / 256, 256>>>(proj, out);
}

// round 13
// speedup vs baseline: 4.1665x; 1.0451x over previous
#include <cuda_runtime.h>
#include <cuda_fp16.h>
#include <cstdint>

typedef unsigned long long u64;
typedef long long           i64;

// ---------------------------------------------------------------------------
#define B_   256
#define T_   100
#define I_   2048
#define H_   2048
#define M_   (B_ * T_)      // 25600

#define BM   64
#define BN   64
#define MT   (M_ / BM)      // 400
#define NT   (H_ / BN)      // 32
#define NCHUNK (I_ / 64)    // 32 K-chunks of 64 fp16 elements (128 bytes/row)

#define NSLICE 3            // 3 digit slices per operand
#define PLANE 8192          // 64 rows x 128 B per digit slice
#define STAGE (2 * NSLICE * PLANE)   // 48 KiB per stage
#define NSTAGES 3
#define DSMEM (NSTAGES * STAGE)      // 144 KiB

#define NTHR 512            // 16 warps: 4 M-groups x 4 N-groups, warp tile m16n16

// Static device scratch (no allocations). Digits stored as fp16 bit patterns.
__device__ __align__(16) unsigned short g_Xs[(i64)NSLICE * M_ * I_];   // 300 MiB
__device__ __align__(16) unsigned short g_Ws[(i64)NSLICE * H_ * I_];   // 24 MiB
__device__ float g_sxf[M_];
__device__ float g_swf[H_];
__device__ float g_proj[(size_t)M_ * H_];                              // 200 MiB

// ---------------------------------------------------------------------------
// helpers (family-common PTX only)
// ---------------------------------------------------------------------------
__device__ __forceinline__ uint32_t smem_u32(const void* p) {
    uint32_t a;
    asm("{ .reg .u64 t; cvta.to.shared.u64 t, %1; cvt.u32.u64 %0, t; }" : "=r"(a) : "l"(p));
    return a;
}
__device__ __forceinline__ uint32_t sw128(uint32_t o) { return o ^ ((o >> 3) & 0x70); }

__device__ __forceinline__ void ldsm4(uint32_t& r0, uint32_t& r1, uint32_t& r2, uint32_t& r3,
                                      uint32_t a) {
    asm volatile("ldmatrix.sync.aligned.m8n8.x4.shared.b16 {%0,%1,%2,%3}, [%4];"
                 : "=r"(r0), "=r"(r1), "=r"(r2), "=r"(r3) : "r"(a));
}
__device__ __forceinline__ void cpa16(uint32_t d, const void* s) {
    asm volatile("cp.async.cg.shared.global [%0], [%1], 16;" :: "r"(d), "l"(s));
}
#define CP_COMMIT() asm volatile("cp.async.commit_group;")
#define CP_WAIT1()  asm volatile("cp.async.wait_group 1;")

// fp16 HMMA, fp32 accumulate (exact: integer digit products, |S| <= 2^24)
#define MMA(d, a, b) \
    asm volatile("mma.sync.aligned.m16n8k16.row.col.f32.f16.f16.f32 " \
                 "{%0,%1,%2,%3}, {%4,%5,%6,%7}, {%8,%9}, {%0,%1,%2,%3};" \
                 : "+f"((d)[0]), "+f"((d)[1]), "+f"((d)[2]), "+f"((d)[3]) \
                 : "r"((a)[0]), "r"((a)[1]), "r"((a)[2]), "r"((a)[3]), \
                   "r"((b)[0]), "r"((b)[1]))

// ---------------------------------------------------------------------------
// Split: per-row power-of-2 scale 2^e (> max|x|), 3 SIGNED digits, exact
// rint peel. X: base-1024 (|d|<=512, u = d0/2^9 + d1/2^19 + d2/2^29, tail 2^-30)
// W: base-512  (|d|<=256, u = d0/2^8 + d1/2^17 + d2/2^26, tail 2^-27)
// All digits exact in fp16. base0/base1 passed as params.
// ---------------------------------------------------------------------------
__global__ __launch_bounds__(256)
void split_kernel(const float* __restrict__ src, unsigned short* __restrict__ dst,
                  float* __restrict__ scl, i64 sstride,
                  float base0, float base1, int sbias)
{
    __shared__ float smax[256];
    __shared__ float s_inv;

    const int r = blockIdx.x;
    const int tid = threadIdx.x;
    const float* row = src + (size_t)r * I_;

    float mx = 0.0f;
    #pragma unroll
    for (int it = 0; it < I_ / 256; it++) mx = fmaxf(mx, fabsf(row[tid + it * 256]));
    smax[tid] = mx;
    __syncthreads();
    for (int s = 128; s > 0; s >>= 1) {
        if (tid < s) smax[tid] = fmaxf(smax[tid], smax[tid + s]);
        __syncthreads();
    }
    if (tid == 0) {
        int e = 0;
        if (smax[0] > 0.0f) frexpf(smax[0], &e);   // max = f*2^e, f in [0.5,1)
        s_inv = ldexpf(1.0f, -e);                  // |u| < 1
        scl[r] = ldexpf(1.0f, e + sbias);          // sbias: -25 (X), -26 (W)
    }
    __syncthreads();
    const float sinv = s_inv;

    #pragma unroll
    for (int it = 0; it < I_ / 256; it++) {
        int k = tid + it * 256;
        float u  = row[k] * sinv;                  // exact, |u| < 1
        float v0 = u * base0;                      // exact, |v0| < base0
        float d0 = rintf(v0);  float r0 = v0 - d0; // exact split
        float v1 = r0 * base1;
        float d1 = rintf(v1);  float r1 = v1 - d1;
        float d2 = rintf(r1 * base1);              // tail dropped

        i64 base = (i64)r * I_ + k;
        // fp32 -> fp16 exact for integers |d| <= 512
        dst[0 * sstride + base] = __half_as_ushort(__float2half_rn(d0));
        dst[1 * sstride + base] = __half_as_ushort(__float2half_rn(d1));
        dst[2 * sstride + base] = __half_as_ushort(__float2half_rn(d2));
    }
}

// ---------------------------------------------------------------------------
// GEMM: fp16 HMMA, 6 digit pairs (i+j<=2), one fp32 accumulator per pair.
// Mixed bases: |dx·dw| <= 512*256 = 2^17, so folding every 2 chunks (128 K)
// keeps |S| <= 2^24 (integer-exact fp32). Fold into signed i64, pair weight
// 2^(34-10i-9j) (P = dot * 2^51). CTA 64x64, 16 warps (4Mx4N), warp m16n16,
// 3-stage cp.async pipeline, ONE __syncthreads per chunk.
// Pair -> accumulator: (0,0)->0 (0,1)->1 (1,0)->2 (0,2)->3 (1,1)->4 (2,0)->5
// ---------------------------------------------------------------------------
__global__ __launch_bounds__(NTHR, 1)
void lif_gemm_hmma_kernel(const float* __restrict__ bias, float* __restrict__ proj)
{
    extern __shared__ int8_t smem[];
    const uint32_t sb = smem_u32(smem);
    const int tid  = threadIdx.x;
    const int lane = tid & 31;
    const int wid  = tid >> 5;
    const int wm   = wid >> 2;    // 0..3 -> M group (16 rows)
    const int wn   = wid & 3;     // 0..3 -> N group (16 cols)
    const int bx = blockIdx.x;    // N tile
    const int by = blockIdx.y;    // M tile

    const int q  = lane >> 3;
    const int l7 = lane & 7;

    float D[6][2][4];   // [pair][nt][e]
    i64   P[2][4];
    #pragma unroll
    for (int s = 0; s < 6; s++)
        #pragma unroll
        for (int nt = 0; nt < 2; nt++)
            #pragma unroll
            for (int e = 0; e < 4; e++) D[s][nt][e] = 0.0f;
    #pragma unroll
    for (int nt = 0; nt < 2; nt++)
        #pragma unroll
        for (int e = 0; e < 4; e++) P[nt][e] = 0ll;

// 6 planes x 512 vec16 = 3072 cp.async per chunk; 6 per thread at 512 thr.
#define LOAD_CHUNK(c) do {                                                        \
    uint32_t stg = sb + ((c) % NSTAGES) * STAGE;                                  \
    _Pragma("unroll")                                                             \
    for (int v = 0; v < 6; v++) {                                                 \
        int id = v * NTHR + tid;                                                  \
        int plane = id >> 9;          /* 0..5: 0-2 A slices, 3-5 B slices */      \
        int idx = id & 511;                                                       \
        int row = idx >> 3, x = idx & 7;                                          \
        uint32_t dst = stg + plane * PLANE                                        \
                     + sw128((uint32_t)(row * 128 + x * 16));                     \
        const unsigned short* src = (plane >= NSLICE)                             \
            ? (g_Ws + (i64)(plane - NSLICE) * H_ * I_ + (i64)(bx * BN + row) * I_ + (c) * 64 + x * 8) \
            : (g_Xs + (i64)plane * M_ * I_ + (i64)(by * BM + row) * I_ + (c) * 64 + x * 8); \
        cpa16(dst, src);                                                          \
    }                                                                             \
    CP_COMMIT();                                                                  \
} while (0)

#define PP(i, j, d) {                                                             \
    MMA(D[d][0], A[i], Bt[j][0]);                                                 \
    MMA(D[d][1], A[i], Bt[j][1]);                                                 \
}

// chunk = 64 fp16 K-elems (128 B rows); ks selects a k16 slab (32 B).
// All 6 pairs use distinct accumulators: zero mma->mma dependencies per step.
#define COMPUTE_CHUNK(c) do {                                                     \
    uint32_t stg = sb + ((c) % NSTAGES) * STAGE;                                  \
    _Pragma("unroll")                                                             \
    for (int ks = 0; ks < 4; ks++) {                                              \
        uint32_t A[NSLICE][4];                                                    \
        _Pragma("unroll")                                                         \
        for (int sl = 0; sl < NSLICE; sl++) {                                     \
            int row = wm * 16 + ((q & 1) << 3) + l7;                              \
            uint32_t ad = stg + sl * PLANE                                        \
                        + sw128((uint32_t)(row * 128 + ks * 32 + (q >> 1) * 16)); \
            ldsm4(A[sl][0], A[sl][1], A[sl][2], A[sl][3], ad);                    \
        }                                                                         \
        uint32_t Bt[NSLICE][2][2];                                                \
        _Pragma("unroll")                                                         \
        for (int sl = 0; sl < NSLICE; sl++) {                                     \
            int n = wn * 16 + ((q & 1) << 3) + l7;                                \
            uint32_t bd = stg + NSLICE * PLANE + sl * PLANE                       \
                        + sw128((uint32_t)(n * 128 + ks * 32 + (q >> 1) * 16));   \
            uint32_t r0, r1, r2, r3;                                              \
            ldsm4(r0, r1, r2, r3, bd);                                            \
            Bt[sl][0][0] = r0; Bt[sl][0][1] = r2;                                 \
            Bt[sl][1][0] = r1; Bt[sl][1][1] = r3;                                 \
        }                                                                         \
        PP(0,0,0) PP(0,1,1) PP(1,0,2) PP(0,2,3) PP(1,1,4) PP(2,0,5)               \
    }                                                                             \
} while (0)

// Fold per-pair fp32 accumulators (exact integers <= 2^24) into signed i64.
// P = dot * 2^51: pair (i,j) weight 2^(51-17-10i-9j):
//   (0,0):34  (0,1):25  (1,0):24  (0,2):16  (1,1):15  (2,0):14
#define FOLD() do {                                                               \
    _Pragma("unroll")                                                             \
    for (int nt = 0; nt < 2; nt++) {                                              \
        _Pragma("unroll")                                                         \
        for (int e = 0; e < 4; e++) {                                             \
            P[nt][e] += ((i64)(int)D[0][nt][e] << 34)                             \
                      + ((i64)(int)D[1][nt][e] << 25)                             \
                      + ((i64)(int)D[2][nt][e] << 24)                             \
                      + ((i64)(int)D[3][nt][e] << 16)                             \
                      + ((i64)(int)D[4][nt][e] << 15)                             \
                      + ((i64)(int)D[5][nt][e] << 14);                            \
            _Pragma("unroll")                                                     \
            for (int s = 0; s < 6; s++) D[s][nt][e] = 0.0f;                       \
        }                                                                         \
    }                                                                             \
} while (0)

    LOAD_CHUNK(0);
    LOAD_CHUNK(1);
    #pragma unroll 1
    for (int c = 0; c < NCHUNK; c++) {
        CP_WAIT1();            // chunk c resident (<=1 group pending)
        __syncthreads();       // all warps see chunk c; compute(c-1) done by all
        if (c + 2 < NCHUNK) LOAD_CHUNK(c + 2);   // overwrites stage (c-1): safe
        COMPUTE_CHUNK(c);
        if (c & 1) FOLD();     // every 128 K: |S| <= 128 * 2^17 = 2^24, exact
    }

    // ---- epilogue: proj = P * 2^(ex+ew-51) + bias, one rounding ----
    const int mrow0 = by * BM + wm * 16 + (lane >> 2);
    const int col0  = bx * BN + wn * 16 + 2 * (lane & 3);

    #pragma unroll
    for (int half = 0; half < 2; half++) {
        int m = mrow0 + 8 * half;
        double sx = (double)g_sxf[m];            // 2^(ex-25)
        float* orow = proj + (size_t)m * H_ + col0;
        #pragma unroll
        for (int nt = 0; nt < 2; nt++) {
            float v[2];
            #pragma unroll
            for (int dj = 0; dj < 2; dj++) {
                int h = col0 + 8 * nt + dj;
                int e = 2 * half + dj;
                double sc = sx * (double)g_swf[h];   // 2^(ex+ew-51), exact
                v[dj] = (float)((double)P[nt][e] * sc + (double)bias[h]);
            }
            *(float2*)(orow + 8 * nt) = make_float2(v[0], v[1]);
        }
    }
#undef LOAD_CHUNK
#undef COMPUTE_CHUNK
#undef PP
#undef FOLD
}

// ---------------------------------------------------------------------------
// LIF scan (measured ~66us, DRAM ~72%)
// ---------------------------------------------------------------------------
__global__ __launch_bounds__(256)
void lif_scan_kernel(const float* __restrict__ proj, float* __restrict__ out)
{
    int idx = blockIdx.x * blockDim.x + threadIdx.x;
    if (idx >= B_ * H_) return;
    int b = idx / H_;
    int h = idx % H_;
    const size_t base = (size_t)b * T_ * H_ + h;
    float hs = 0.0f;
    #pragma unroll 4
    for (int t = 0; t < T_; t++) {
        float p = proj[base + (size_t)t * H_];
        hs = __fadd_rn(__fmul_rn(0.9f, hs), p);
        float sp = (hs >= 1.0f) ? 1.0f : 0.0f;
        out[base + (size_t)t * H_] = sp;
        hs = __fmul_rn(hs, __fsub_rn(1.0f, sp));
    }
    out[(size_t)B_ * T_ * H_ + (size_t)b * H_ + h] = hs;
}

// ---------------------------------------------------------------------------
extern "C" void kernel_launch(void* const* d_in, const int* in_sizes, int n_in,
                              void* d_out, int out_size)
{
    const float* X    = (const float*)d_in[0];
    const float* W    = (const float*)d_in[1];
    const float* bias = (const float*)d_in[2];
    float* out = (float*)d_out;

    unsigned short *Xs, *Ws;
    float *sxf, *swf, *proj;
    cudaGetSymbolAddress((void**)&Xs, g_Xs);
    cudaGetSymbolAddress((void**)&Ws, g_Ws);
    cudaGetSymbolAddress((void**)&sxf, g_sxf);
    cudaGetSymbolAddress((void**)&swf, g_swf);
    cudaGetSymbolAddress((void**)&proj, g_proj);

    cudaFuncSetAttribute(lif_gemm_hmma_kernel,
                         cudaFuncAttributeMaxDynamicSharedMemorySize, DSMEM);

    // digit splits: X base-1024 (|d|<=512), W base-512 (|d|<=256)
    split_kernel<<<M_, 256>>>(X, Xs, sxf, (i64)M_ * I_, 512.0f, 1024.0f, -25);
    split_kernel<<<H_, 256>>>(W, Ws, swf, (i64)H_ * I_, 256.0f,  512.0f, -26);

    // fp16 HMMA GEMM, 6 pairs, exact integer recombination
    dim3 ggrid(NT, MT);   // (32, 400): bx fastest -> X tiles shared in L2
    lif_gemm_hmma_kernel<<<ggrid, NTHR, DSMEM>>>(bias, proj);

    // LIF scan
    lif_scan_kernel<<<(B_ * H_ + 255) / 256, 256>>>(proj, out);
}

// round 14
// speedup vs baseline: 4.5791x; 1.0990x over previous
#include <cuda_runtime.h>
#include <cuda_fp16.h>
#include <cstdint>

typedef unsigned long long u64;
typedef long long           i64;

// ---------------------------------------------------------------------------
#define B_   256
#define T_   100
#define I_   2048
#define H_   2048
#define M_   (B_ * T_)      // 25600

#define BM   64
#define BN   128
#define MT   (M_ / BM)      // 400
#define NT   (H_ / BN)      // 16
#define NCHUNK (I_ / 64)    // 32 K-chunks of 64 fp16 elements (128 bytes/row)

#define NSLICE 3            // base-512 digits: 3 slices per operand
#define PLANE_A 8192        // 64 rows x 128 B
#define PLANE_B 16384       // 128 rows x 128 B
#define OFF_B   (NSLICE * PLANE_A)               // 24576
#define STAGE   (OFF_B + NSLICE * PLANE_B)       // 73728
#define NSTAGES 3
#define DSMEM   (NSTAGES * STAGE)                // 221184 (< 227 KB cap)

#define NTHR 256            // 8 warps: 2 M-groups x 4 N-groups, warp tile m32n32

// Static device scratch (no allocations). Digits stored as fp16 bit patterns.
__device__ __align__(16) unsigned short g_Xs[(i64)NSLICE * M_ * I_];   // 300 MiB
__device__ __align__(16) unsigned short g_Ws[(i64)NSLICE * H_ * I_];   // 24 MiB
__device__ float g_sxf[M_];
__device__ float g_swf[H_];
__device__ float g_proj[(size_t)M_ * H_];                              // 200 MiB

// ---------------------------------------------------------------------------
// helpers (family-common PTX only)
// ---------------------------------------------------------------------------
__device__ __forceinline__ uint32_t smem_u32(const void* p) {
    uint32_t a;
    asm("{ .reg .u64 t; cvta.to.shared.u64 t, %1; cvt.u32.u64 %0, t; }" : "=r"(a) : "l"(p));
    return a;
}
__device__ __forceinline__ uint32_t sw128(uint32_t o) { return o ^ ((o >> 3) & 0x70); }

__device__ __forceinline__ void ldsm4(uint32_t& r0, uint32_t& r1, uint32_t& r2, uint32_t& r3,
                                      uint32_t a) {
    asm volatile("ldmatrix.sync.aligned.m8n8.x4.shared.b16 {%0,%1,%2,%3}, [%4];"
                 : "=r"(r0), "=r"(r1), "=r"(r2), "=r"(r3) : "r"(a));
}
__device__ __forceinline__ void cpa16(uint32_t d, const void* s) {
    asm volatile("cp.async.cg.shared.global [%0], [%1], 16;" :: "r"(d), "l"(s));
}
#define CP_COMMIT() asm volatile("cp.async.commit_group;")
#define CP_WAIT1()  asm volatile("cp.async.wait_group 1;")

// fp16 HMMA, fp32 accumulate (exact: integer digit products, |S| <= 2^24)
#define MMA(d, a, b) \
    asm volatile("mma.sync.aligned.m16n8k16.row.col.f32.f16.f16.f32 " \
                 "{%0,%1,%2,%3}, {%4,%5,%6,%7}, {%8,%9}, {%0,%1,%2,%3};" \
                 : "+f"((d)[0]), "+f"((d)[1]), "+f"((d)[2]), "+f"((d)[3]) \
                 : "r"((a)[0]), "r"((a)[1]), "r"((a)[2]), "r"((a)[3]), \
                   "r"((b)[0]), "r"((b)[1]))

// ---------------------------------------------------------------------------
// Split: per-row power-of-2 scale 2^e (> max|x|), 3 SIGNED base-512 digits:
// u = d0/2^8 + d1/2^17 + d2/2^26 + tail (|tail| <= 2^-27), |d_i| <= 256,
// all peel steps exact fp32. Digits exact in fp16. (Same scheme as R11 which
// matched the exact-GEMM rel_err.)
// ---------------------------------------------------------------------------
__global__ __launch_bounds__(256)
void split_kernel(const float* __restrict__ src, unsigned short* __restrict__ dst,
                  float* __restrict__ scl, i64 sstride)
{
    __shared__ float smax[256];
    __shared__ float s_inv;

    const int r = blockIdx.x;
    const int tid = threadIdx.x;
    const float* row = src + (size_t)r * I_;

    float mx = 0.0f;
    #pragma unroll
    for (int it = 0; it < I_ / 256; it++) mx = fmaxf(mx, fabsf(row[tid + it * 256]));
    smax[tid] = mx;
    __syncthreads();
    for (int s = 128; s > 0; s >>= 1) {
        if (tid < s) smax[tid] = fmaxf(smax[tid], smax[tid + s]);
        __syncthreads();
    }
    if (tid == 0) {
        int e = 0;
        if (smax[0] > 0.0f) frexpf(smax[0], &e);   // max = f*2^e, f in [0.5,1)
        s_inv = ldexpf(1.0f, -e);                  // |u| < 1
        scl[r] = ldexpf(1.0f, e - 17);             // pair scale: 2^(ex+ew-34)
    }
    __syncthreads();
    const float sinv = s_inv;

    #pragma unroll
    for (int it = 0; it < I_ / 256; it++) {
        int k = tid + it * 256;
        float u  = row[k] * sinv;                  // exact, |u| < 1
        float v0 = u * 256.0f;                     // exact, |v0| < 256
        float d0 = rintf(v0);  float r0 = v0 - d0; // exact, |d0|<=256
        float v1 = r0 * 512.0f;
        float d1 = rintf(v1);  float r1 = v1 - d1; // |d1|<=256
        float d2 = rintf(r1 * 512.0f);             // |d2|<=256, tail 2^-27 dropped

        i64 base = (i64)r * I_ + k;
        dst[0 * sstride + base] = __half_as_ushort(__float2half_rn(d0));
        dst[1 * sstride + base] = __half_as_ushort(__float2half_rn(d1));
        dst[2 * sstride + base] = __half_as_ushort(__float2half_rn(d2));
    }
}

// ---------------------------------------------------------------------------
// GEMM: fp16 HMMA, 6 digit pairs (i+j<=2). Equal bases -> pair weight depends
// only on s=i+j: THREE shared-s fp32 accumulator sets (exact: worst set s=2
// has 3 pairs * 64 K * 2^16 = 1.26e7 < 2^24 per chunk; fold every chunk).
// P = (u.v)*2^34 in i64 (|P| <= 2^45, exact in double at the end).
// CTA 64x128, 8 warps (2M x 4N), warp tile m32n32 -> ldsm bytes/mma = 128
// (half of the m16n16 layout). 3-stage cp.async pipeline, 1 sync per chunk.
// ---------------------------------------------------------------------------
__global__ __launch_bounds__(NTHR, 1)
void lif_gemm_hmma_kernel(const float* __restrict__ bias, float* __restrict__ proj)
{
    extern __shared__ int8_t smem[];
    const uint32_t sb = smem_u32(smem);
    const int tid  = threadIdx.x;
    const int lane = tid & 31;
    const int wid  = tid >> 5;
    const int wm   = wid >> 2;    // 0..1 -> M group (32 rows)
    const int wn   = wid & 3;     // 0..3 -> N group (32 cols)
    const int bx = blockIdx.x;    // N tile (128)
    const int by = blockIdx.y;    // M tile (64)

    const int q  = lane >> 3;
    const int l7 = lane & 7;

    float D[3][8][4];   // [s][tile = mt*4+nt][e]
    i64   P[8][4];
    #pragma unroll
    for (int s = 0; s < 3; s++)
        #pragma unroll
        for (int t = 0; t < 8; t++)
            #pragma unroll
            for (int e = 0; e < 4; e++) D[s][t][e] = 0.0f;
    #pragma unroll
    for (int t = 0; t < 8; t++)
        #pragma unroll
        for (int e = 0; e < 4; e++) P[t][e] = 0ll;

// chunk = A 24KB (3 planes x 64 rows) + B 48KB (3 planes x 128 rows) = 4608
// vec16; 18 per thread at 256 thr. v 0..5 -> A (uniform), v 6..17 -> B.
#define LOAD_CHUNK(c) do {                                                        \
    uint32_t stg = sb + ((c) % NSTAGES) * STAGE;                                  \
    _Pragma("unroll")                                                             \
    for (int v = 0; v < 6; v++) {                                                 \
        int id = v * NTHR + tid;                                                  \
        int sl = id >> 9;                                                         \
        int idx = id & 511;                                                       \
        int row = idx >> 3, x = idx & 7;                                          \
        uint32_t dst = stg + sl * PLANE_A + sw128((uint32_t)(row * 128 + x * 16));\
        cpa16(dst, g_Xs + (i64)sl * M_ * I_ + (i64)(by * BM + row) * I_           \
                       + (c) * 64 + x * 8);                                       \
    }                                                                             \
    _Pragma("unroll")                                                             \
    for (int v = 0; v < 12; v++) {                                                \
        int id = v * NTHR + tid;                                                  \
        int sl = id >> 10;                                                        \
        int idx = id & 1023;                                                      \
        int row = idx >> 3, x = idx & 7;                                          \
        uint32_t dst = stg + OFF_B + sl * PLANE_B                                 \
                     + sw128((uint32_t)(row * 128 + x * 16));                     \
        cpa16(dst, g_Ws + (i64)sl * H_ * I_ + (i64)(bx * BN + row) * I_           \
                       + (c) * 64 + x * 8);                                       \
    }                                                                             \
    CP_COMMIT();                                                                  \
} while (0)

// pair (i,j) -> accumulator set s=i+j; 8 m16n8 tile-mma per pair (m32 x n32)
#define PP(i, j, s) {                                                             \
    _Pragma("unroll")                                                             \
    for (int mt = 0; mt < 2; mt++)                                                \
        _Pragma("unroll")                                                         \
        for (int nt = 0; nt < 4; nt++)                                            \
            MMA(D[s][mt * 4 + nt], A[i][mt], Bt[j][nt]);                          \
}

#define COMPUTE_CHUNK(c) do {                                                     \
    uint32_t stg = sb + ((c) % NSTAGES) * STAGE;                                  \
    _Pragma("unroll")                                                             \
    for (int ks = 0; ks < 4; ks++) {                                              \
        uint32_t A[NSLICE][2][4];                                                 \
        _Pragma("unroll")                                                         \
        for (int sl = 0; sl < NSLICE; sl++) {                                     \
            _Pragma("unroll")                                                     \
            for (int mt = 0; mt < 2; mt++) {                                      \
                int row = wm * 32 + mt * 16 + ((q & 1) << 3) + l7;                \
                uint32_t ad = stg + sl * PLANE_A                                  \
                            + sw128((uint32_t)(row * 128 + ks * 32 + (q >> 1) * 16)); \
                ldsm4(A[sl][mt][0], A[sl][mt][1], A[sl][mt][2], A[sl][mt][3], ad);\
            }                                                                     \
        }                                                                         \
        uint32_t Bt[NSLICE][4][2];                                                \
        _Pragma("unroll")                                                         \
        for (int sl = 0; sl < NSLICE; sl++) {                                     \
            _Pragma("unroll")                                                     \
            for (int g = 0; g < 2; g++) {                                         \
                int n = wn * 32 + g * 16 + ((q & 1) << 3) + l7;                   \
                uint32_t bd = stg + OFF_B + sl * PLANE_B                          \
                            + sw128((uint32_t)(n * 128 + ks * 32 + (q >> 1) * 16)); \
                uint32_t r0, r1, r2, r3;                                          \
                ldsm4(r0, r1, r2, r3, bd);                                        \
                Bt[sl][2 * g][0] = r0;     Bt[sl][2 * g][1] = r2;                 \
                Bt[sl][2 * g + 1][0] = r1; Bt[sl][2 * g + 1][1] = r3;             \
            }                                                                     \
        }                                                                         \
        PP(0,0,0) PP(0,1,1) PP(0,2,2) PP(1,0,1) PP(1,1,2) PP(2,0,2)               \
    }                                                                             \
} while (0)

// Fold shared-s fp32 accumulators (exact integers < 2^24) into signed i64:
// u*v*2^34 = S0*2^18 + S1*2^9 + S2 (+ dropped 2^-27 tails)
#define FOLD() do {                                                               \
    _Pragma("unroll")                                                             \
    for (int t = 0; t < 8; t++) {                                                 \
        _Pragma("unroll")                                                         \
        for (int e = 0; e < 4; e++) {                                             \
            P[t][e] += ((i64)(int)D[0][t][e] << 18)                               \
                     + ((i64)(int)D[1][t][e] << 9)                                \
                     +  (i64)(int)D[2][t][e];                                     \
            D[0][t][e] = 0.0f; D[1][t][e] = 0.0f; D[2][t][e] = 0.0f;              \
        }                                                                         \
    }                                                                             \
} while (0)

    LOAD_CHUNK(0);
    LOAD_CHUNK(1);
    #pragma unroll 1
    for (int c = 0; c < NCHUNK; c++) {
        CP_WAIT1();            // chunk c resident (<=1 group pending)
        __syncthreads();       // all warps see chunk c; compute(c-1) done
        if (c + 2 < NCHUNK) LOAD_CHUNK(c + 2);   // overwrites stage (c-1): safe
        COMPUTE_CHUNK(c);
        FOLD();                // every chunk: |S2| <= 3*64*2^16 = 1.26e7 < 2^24
    }

    // ---- epilogue: proj = P * 2^(ex+ew-34) + bias, one rounding ----
    #pragma unroll
    for (int mt = 0; mt < 2; mt++) {
        #pragma unroll
        for (int half = 0; half < 2; half++) {
            int m = by * BM + wm * 32 + mt * 16 + 8 * half + (lane >> 2);
            double sx = (double)g_sxf[m];            // 2^(ex-17)
            float* orow = proj + (size_t)m * H_ + bx * BN + wn * 32 + 2 * (lane & 3);
            #pragma unroll
            for (int nt = 0; nt < 4; nt++) {
                int t = mt * 4 + nt;
                float v[2];
                #pragma unroll
                for (int dj = 0; dj < 2; dj++) {
                    int h = bx * BN + wn * 32 + nt * 8 + 2 * (lane & 3) + dj;
                    int e = 2 * half + dj;
                    double sc = sx * (double)g_swf[h];   // 2^(ex+ew-34), exact
                    v[dj] = (float)((double)P[t][e] * sc + (double)bias[h]);
                }
                *(float2*)(orow + nt * 8) = make_float2(v[0], v[1]);
            }
        }
    }
#undef LOAD_CHUNK
#undef COMPUTE_CHUNK
#undef PP
#undef FOLD
}

// ---------------------------------------------------------------------------
// LIF scan (measured ~66us, DRAM ~72%)
// ---------------------------------------------------------------------------
__global__ __launch_bounds__(256)
void lif_scan_kernel(const float* __restrict__ proj, float* __restrict__ out)
{
    int idx = blockIdx.x * blockDim.x + threadIdx.x;
    if (idx >= B_ * H_) return;
    int b = idx / H_;
    int h = idx % H_;
    const size_t base = (size_t)b * T_ * H_ + h;
    float hs = 0.0f;
    #pragma unroll 4
    for (int t = 0; t < T_; t++) {
        float p = proj[base + (size_t)t * H_];
        hs = __fadd_rn(__fmul_rn(0.9f, hs), p);
        float sp = (hs >= 1.0f) ? 1.0f : 0.0f;
        out[base + (size_t)t * H_] = sp;
        hs = __fmul_rn(hs, __fsub_rn(1.0f, sp));
    }
    out[(size_t)B_ * T_ * H_ + (size_t)b * H_ + h] = hs;
}

// ---------------------------------------------------------------------------
extern "C" void kernel_launch(void* const* d_in, const int* in_sizes, int n_in,
                              void* d_out, int out_size)
{
    const float* X    = (const float*)d_in[0];
    const float* W    = (const float*)d_in[1];
    const float* bias = (const float*)d_in[2];
    float* out = (float*)d_out;

    unsigned short *Xs, *Ws;
    float *sxf, *swf, *proj;
    cudaGetSymbolAddress((void**)&Xs, g_Xs);
    cudaGetSymbolAddress((void**)&Ws, g_Ws);
    cudaGetSymbolAddress((void**)&sxf, g_sxf);
    cudaGetSymbolAddress((void**)&swf, g_swf);
    cudaGetSymbolAddress((void**)&proj, g_proj);

    cudaFuncSetAttribute(lif_gemm_hmma_kernel,
                         cudaFuncAttributeMaxDynamicSharedMemorySize, DSMEM);

    // signed base-512 digit splits (3 fp16 planes per operand)
    split_kernel<<<M_, 256>>>(X, Xs, sxf, (i64)M_ * I_);
    split_kernel<<<H_, 256>>>(W, Ws, swf, (i64)H_ * I_);

    // fp16 HMMA GEMM, 6 pairs, shared-s accumulators, exact recombination
    dim3 ggrid(NT, MT);   // (16, 400): bx fastest -> X tiles shared in L2
    lif_gemm_hmma_kernel<<<ggrid, NTHR, DSMEM>>>(bias, proj);

    // LIF scan
    lif_scan_kernel<<<(B_ * H_ + 255) / 256, 256>>>(proj, out);
}

// round 15
// speedup vs baseline: 4.9914x; 1.0900x over previous
#include <cuda_runtime.h>
#include <cuda_fp16.h>
#include <cstdint>

typedef unsigned long long u64;
typedef long long           i64;

// ---------------------------------------------------------------------------
#define B_   256
#define T_   100
#define I_   2048
#define H_   2048
#define M_   (B_ * T_)      // 25600

#define BM   64
#define BN   128
#define MT   (M_ / BM)      // 400
#define NT   (H_ / BN)      // 16
#define NCHUNK (I_ / 64)    // 32 K-chunks of 64 fp16 elements (128 bytes/row)

#define NSLICE 3            // base-512 digits: 3 slices per operand
#define PLANE_A 8192        // 64 rows x 128 B
#define PLANE_B 16384       // 128 rows x 128 B
#define OFF_B   (NSLICE * PLANE_A)               // 24576
#define STAGE   (OFF_B + NSLICE * PLANE_B)       // 73728
#define NSTAGES 3
#define DSMEM   (NSTAGES * STAGE)                // 221184 (< 227 KB cap)

#define NTHR 256            // 8 warps: 2 M-groups x 4 N-groups, warp tile m32n32

// Static device scratch (no allocations). Digits stored as fp16 bit patterns.
__device__ __align__(16) unsigned short g_Xs[(i64)NSLICE * M_ * I_];   // 300 MiB
__device__ __align__(16) unsigned short g_Ws[(i64)NSLICE * H_ * I_];   // 24 MiB
__device__ float g_sxf[M_];
__device__ float g_swf[H_];
__device__ float g_proj[(size_t)M_ * H_];                              // 200 MiB

// ---------------------------------------------------------------------------
// helpers (family-common PTX only)
// ---------------------------------------------------------------------------
__device__ __forceinline__ uint32_t smem_u32(const void* p) {
    uint32_t a;
    asm("{ .reg .u64 t; cvta.to.shared.u64 t, %1; cvt.u32.u64 %0, t; }" : "=r"(a) : "l"(p));
    return a;
}
__device__ __forceinline__ uint32_t sw128(uint32_t o) { return o ^ ((o >> 3) & 0x70); }

__device__ __forceinline__ void ldsm4(uint32_t& r0, uint32_t& r1, uint32_t& r2, uint32_t& r3,
                                      uint32_t a) {
    asm volatile("ldmatrix.sync.aligned.m8n8.x4.shared.b16 {%0,%1,%2,%3}, [%4];"
                 : "=r"(r0), "=r"(r1), "=r"(r2), "=r"(r3) : "r"(a));
}
__device__ __forceinline__ void cpa16(uint32_t d, const void* s) {
    asm volatile("cp.async.cg.shared.global [%0], [%1], 16;" :: "r"(d), "l"(s));
}
#define CP_COMMIT() asm volatile("cp.async.commit_group;")
#define CP_WAIT1()  asm volatile("cp.async.wait_group 1;")

// fp16 HMMA, fp32 accumulate (exact: integer digit products, |S| <= 2^24)
#define MMA(d, a, b) \
    asm volatile("mma.sync.aligned.m16n8k16.row.col.f32.f16.f16.f32 " \
                 "{%0,%1,%2,%3}, {%4,%5,%6,%7}, {%8,%9}, {%0,%1,%2,%3};" \
                 : "+f"((d)[0]), "+f"((d)[1]), "+f"((d)[2]), "+f"((d)[3]) \
                 : "r"((a)[0]), "r"((a)[1]), "r"((a)[2]), "r"((a)[3]), \
                   "r"((b)[0]), "r"((b)[1]))

// ---------------------------------------------------------------------------
// Split: per-row power-of-2 scale 2^e (> max|x|), 3 SIGNED base-512 digits:
// u = d0/2^8 + d1/2^17 + d2/2^26 + tail (|tail| <= 2^-27), |d_i| <= 256,
// all peel steps exact fp32. Digits exact in fp16.
// *** NUMERICS FROZEN: this exact scheme produced rel_err 4.1e-7 in R14. ***
// ---------------------------------------------------------------------------
__global__ __launch_bounds__(256)
void split_kernel(const float* __restrict__ src, unsigned short* __restrict__ dst,
                  float* __restrict__ scl, i64 sstride)
{
    __shared__ float smax[256];
    __shared__ float s_inv;

    const int r = blockIdx.x;
    const int tid = threadIdx.x;
    const float* row = src + (size_t)r * I_;

    float mx = 0.0f;
    #pragma unroll
    for (int it = 0; it < I_ / 256; it++) mx = fmaxf(mx, fabsf(row[tid + it * 256]));
    smax[tid] = mx;
    __syncthreads();
    for (int s = 128; s > 0; s >>= 1) {
        if (tid < s) smax[tid] = fmaxf(smax[tid], smax[tid + s]);
        __syncthreads();
    }
    if (tid == 0) {
        int e = 0;
        if (smax[0] > 0.0f) frexpf(smax[0], &e);   // max = f*2^e, f in [0.5,1)
        s_inv = ldexpf(1.0f, -e);                  // |u| < 1
        scl[r] = ldexpf(1.0f, e - 17);             // pair scale: 2^(ex+ew-34)
    }
    __syncthreads();
    const float sinv = s_inv;

    #pragma unroll
    for (int it = 0; it < I_ / 256; it++) {
        int k = tid + it * 256;
        float u  = row[k] * sinv;                  // exact, |u| < 1
        float v0 = u * 256.0f;                     // exact, |v0| < 256
        float d0 = rintf(v0);  float r0 = v0 - d0; // exact, |d0|<=256
        float v1 = r0 * 512.0f;
        float d1 = rintf(v1);  float r1 = v1 - d1; // |d1|<=256
        float d2 = rintf(r1 * 512.0f);             // |d2|<=256, tail 2^-27 dropped

        i64 base = (i64)r * I_ + k;
        dst[0 * sstride + base] = __half_as_ushort(__float2half_rn(d0));
        dst[1 * sstride + base] = __half_as_ushort(__float2half_rn(d1));
        dst[2 * sstride + base] = __half_as_ushort(__float2half_rn(d2));
    }
}

// ---------------------------------------------------------------------------
// GEMM: fp16 HMMA, 6 digit pairs (i+j<=2), THREE shared-s fp32 accumulator
// sets. STAGGERED exact folds (all bounds inclusive-representable at 2^24):
//   s=2 (3 pairs): fold every chunk   (3*64*2^16  = 2^23.58)
//   s=1 (2 pairs): fold every 2 chunks (2*128*2^16 = 2^24)
//   s=0 (1 pair) : fold every 4 chunks (1*256*2^16 = 2^24)
// Integer sums are order-independent -> P bit-identical to R14.
// CTA 64x128, 8 warps (2M x 4N), warp tile m32n32, 3-stage cp.async pipeline.
// ---------------------------------------------------------------------------
__global__ __launch_bounds__(NTHR, 1)
void lif_gemm_hmma_kernel(const float* __restrict__ bias, float* __restrict__ proj)
{
    extern __shared__ int8_t smem[];
    const uint32_t sb = smem_u32(smem);
    const int tid  = threadIdx.x;
    const int lane = tid & 31;
    const int wid  = tid >> 5;
    const int wm   = wid >> 2;    // 0..1 -> M group (32 rows)
    const int wn   = wid & 3;     // 0..3 -> N group (32 cols)
    const int bx = blockIdx.x;    // N tile (128)
    const int by = blockIdx.y;    // M tile (64)

    const int q  = lane >> 3;
    const int l7 = lane & 7;

    float D[3][8][4];   // [s][tile = mt*4+nt][e]
    i64   P[8][4];
    #pragma unroll
    for (int s = 0; s < 3; s++)
        #pragma unroll
        for (int t = 0; t < 8; t++)
            #pragma unroll
            for (int e = 0; e < 4; e++) D[s][t][e] = 0.0f;
    #pragma unroll
    for (int t = 0; t < 8; t++)
        #pragma unroll
        for (int e = 0; e < 4; e++) P[t][e] = 0ll;

// chunk = A 24KB (3 planes x 64 rows) + B 48KB (3 planes x 128 rows) = 4608
// vec16; 18 per thread at 256 thr. v 0..5 -> A, v 6..17 -> B.
#define LOAD_CHUNK(c) do {                                                        \
    uint32_t stg = sb + ((c) % NSTAGES) * STAGE;                                  \
    _Pragma("unroll")                                                             \
    for (int v = 0; v < 6; v++) {                                                 \
        int id = v * NTHR + tid;                                                  \
        int sl = id >> 9;                                                         \
        int idx = id & 511;                                                       \
        int row = idx >> 3, x = idx & 7;                                          \
        uint32_t dst = stg + sl * PLANE_A + sw128((uint32_t)(row * 128 + x * 16));\
        cpa16(dst, g_Xs + (i64)sl * M_ * I_ + (i64)(by * BM + row) * I_           \
                       + (c) * 64 + x * 8);                                       \
    }                                                                             \
    _Pragma("unroll")                                                             \
    for (int v = 0; v < 12; v++) {                                                \
        int id = v * NTHR + tid;                                                  \
        int sl = id >> 10;                                                        \
        int idx = id & 1023;                                                      \
        int row = idx >> 3, x = idx & 7;                                          \
        uint32_t dst = stg + OFF_B + sl * PLANE_B                                 \
                     + sw128((uint32_t)(row * 128 + x * 16));                     \
        cpa16(dst, g_Ws + (i64)sl * H_ * I_ + (i64)(bx * BN + row) * I_           \
                       + (c) * 64 + x * 8);                                       \
    }                                                                             \
    CP_COMMIT();                                                                  \
} while (0)

// pair (i,j) -> accumulator set s=i+j; 8 m16n8 tile-mma per pair (m32 x n32)
#define PP(i, j, s) {                                                             \
    _Pragma("unroll")                                                             \
    for (int mt = 0; mt < 2; mt++)                                                \
        _Pragma("unroll")                                                         \
        for (int nt = 0; nt < 4; nt++)                                            \
            MMA(D[s][mt * 4 + nt], A[i][mt], Bt[j][nt]);                          \
}

#define COMPUTE_CHUNK(c) do {                                                     \
    uint32_t stg = sb + ((c) % NSTAGES) * STAGE;                                  \
    _Pragma("unroll")                                                             \
    for (int ks = 0; ks < 4; ks++) {                                              \
        uint32_t A[NSLICE][2][4];                                                 \
        _Pragma("unroll")                                                         \
        for (int sl = 0; sl < NSLICE; sl++) {                                     \
            _Pragma("unroll")                                                     \
            for (int mt = 0; mt < 2; mt++) {                                      \
                int row = wm * 32 + mt * 16 + ((q & 1) << 3) + l7;                \
                uint32_t ad = stg + sl * PLANE_A                                  \
                            + sw128((uint32_t)(row * 128 + ks * 32 + (q >> 1) * 16)); \
                ldsm4(A[sl][mt][0], A[sl][mt][1], A[sl][mt][2], A[sl][mt][3], ad);\
            }                                                                     \
        }                                                                         \
        uint32_t Bt[NSLICE][4][2];                                                \
        _Pragma("unroll")                                                         \
        for (int sl = 0; sl < NSLICE; sl++) {                                     \
            _Pragma("unroll")                                                     \
            for (int g = 0; g < 2; g++) {                                         \
                int n = wn * 32 + g * 16 + ((q & 1) << 3) + l7;                   \
                uint32_t bd = stg + OFF_B + sl * PLANE_B                          \
                            + sw128((uint32_t)(n * 128 + ks * 32 + (q >> 1) * 16)); \
                uint32_t r0, r1, r2, r3;                                          \
                ldsm4(r0, r1, r2, r3, bd);                                        \
                Bt[sl][2 * g][0] = r0;     Bt[sl][2 * g][1] = r2;                 \
                Bt[sl][2 * g + 1][0] = r1; Bt[sl][2 * g + 1][1] = r3;             \
            }                                                                     \
        }                                                                         \
        PP(0,0,0) PP(0,1,1) PP(0,2,2) PP(1,0,1) PP(1,1,2) PP(2,0,2)               \
    }                                                                             \
} while (0)

// Staggered fold of ONE accumulator set into P (shift = 9*(2-s)).
#define FOLD_S(s, shift) do {                                                     \
    _Pragma("unroll")                                                             \
    for (int t = 0; t < 8; t++) {                                                 \
        _Pragma("unroll")                                                         \
        for (int e = 0; e < 4; e++) {                                             \
            P[t][e] += ((i64)(int)D[s][t][e] << (shift));                         \
            D[s][t][e] = 0.0f;                                                    \
        }                                                                         \
    }                                                                             \
} while (0)

    LOAD_CHUNK(0);
    LOAD_CHUNK(1);
    #pragma unroll 1
    for (int c = 0; c < NCHUNK; c++) {
        CP_WAIT1();            // chunk c resident (<=1 group pending)
        __syncthreads();       // all warps see chunk c; compute(c-1) done
        if (c + 2 < NCHUNK) LOAD_CHUNK(c + 2);   // overwrites stage (c-1): safe
        COMPUTE_CHUNK(c);
        FOLD_S(2, 0);                       // every chunk
        if ((c & 1) == 1) FOLD_S(1, 9);     // every 2 chunks
        if ((c & 3) == 3) FOLD_S(0, 18);    // every 4 chunks (NCHUNK%4==0)
    }

    // ---- epilogue: proj = P * 2^(ex+ew-34) + bias, one rounding ----
    #pragma unroll
    for (int mt = 0; mt < 2; mt++) {
        #pragma unroll
        for (int half = 0; half < 2; half++) {
            int m = by * BM + wm * 32 + mt * 16 + 8 * half + (lane >> 2);
            double sx = (double)g_sxf[m];            // 2^(ex-17)
            float* orow = proj + (size_t)m * H_ + bx * BN + wn * 32 + 2 * (lane & 3);
            #pragma unroll
            for (int nt = 0; nt < 4; nt++) {
                int t = mt * 4 + nt;
                float v[2];
                #pragma unroll
                for (int dj = 0; dj < 2; dj++) {
                    int h = bx * BN + wn * 32 + nt * 8 + 2 * (lane & 3) + dj;
                    int e = 2 * half + dj;
                    double sc = sx * (double)g_swf[h];   // 2^(ex+ew-34), exact
                    v[dj] = (float)((double)P[t][e] * sc + (double)bias[h]);
                }
                *(float2*)(orow + nt * 8) = make_float2(v[0], v[1]);
            }
        }
    }
#undef LOAD_CHUNK
#undef COMPUTE_CHUNK
#undef PP
#undef FOLD_S
}

// ---------------------------------------------------------------------------
// LIF scan (measured ~66us, DRAM ~72%)
// ---------------------------------------------------------------------------
__global__ __launch_bounds__(256)
void lif_scan_kernel(const float* __restrict__ proj, float* __restrict__ out)
{
    int idx = blockIdx.x * blockDim.x + threadIdx.x;
    if (idx >= B_ * H_) return;
    int b = idx / H_;
    int h = idx % H_;
    const size_t base = (size_t)b * T_ * H_ + h;
    float hs = 0.0f;
    #pragma unroll 4
    for (int t = 0; t < T_; t++) {
        float p = proj[base + (size_t)t * H_];
        hs = __fadd_rn(__fmul_rn(0.9f, hs), p);
        float sp = (hs >= 1.0f) ? 1.0f : 0.0f;
        out[base + (size_t)t * H_] = sp;
        hs = __fmul_rn(hs, __fsub_rn(1.0f, sp));
    }
    out[(size_t)B_ * T_ * H_ + (size_t)b * H_ + h] = hs;
}

// ---------------------------------------------------------------------------
extern "C" void kernel_launch(void* const* d_in, const int* in_sizes, int n_in,
                              void* d_out, int out_size)
{
    const float* X    = (const float*)d_in[0];
    const float* W    = (const float*)d_in[1];
    const float* bias = (const float*)d_in[2];
    float* out = (float*)d_out;

    unsigned short *Xs, *Ws;
    float *sxf, *swf, *proj;
    cudaGetSymbolAddress((void**)&Xs, g_Xs);
    cudaGetSymbolAddress((void**)&Ws, g_Ws);
    cudaGetSymbolAddress((void**)&sxf, g_sxf);
    cudaGetSymbolAddress((void**)&swf, g_swf);
    cudaGetSymbolAddress((void**)&proj, g_proj);

    cudaFuncSetAttribute(lif_gemm_hmma_kernel,
                         cudaFuncAttributeMaxDynamicSharedMemorySize, DSMEM);

    // signed base-512 digit splits (3 fp16 planes per operand) — FROZEN
    split_kernel<<<M_, 256>>>(X, Xs, sxf, (i64)M_ * I_);
    split_kernel<<<H_, 256>>>(W, Ws, swf, (i64)H_ * I_);

    // fp16 HMMA GEMM, 6 pairs, staggered exact folds (bit-identical output)
    dim3 ggrid(NT, MT);   // (16, 400): bx fastest -> X tiles shared in L2
    lif_gemm_hmma_kernel<<<ggrid, NTHR, DSMEM>>>(bias, proj);

    // LIF scan
    lif_scan_kernel<<<(B_ * H_ + 255) / 256, 256>>>(proj, out);
}